// round 1
// baseline (speedup 1.0000x reference)
#include <cuda_runtime.h>
#include <math.h>

#define BATCH 4
#define NPTS  8192
#define KNB   16
#define NPOS  (BATCH*NPTS*KNB)   // 524288

// -------- scratch (device globals; no allocation) --------
__device__ int   g_idx[BATCH*NPTS*KNB];            // 2 MB
__device__ float g_h1[(long long)NPOS*64];         // 134 MB
__device__ float g_x1[BATCH*NPTS*64];              // 8 MB

__device__ __forceinline__ float leaky(float v) { return v >= 0.f ? v : 0.2f*v; }

// =====================================================================
// Kernel 1: KNN (top-16 smallest d2, set semantics; self included, d2=0)
// =====================================================================
__global__ __launch_bounds__(256) void knn_kernel(const float* __restrict__ xyz)
{
    __shared__ float sx[4096], sy[4096], sz[4096];
    const int tid = threadIdx.x;
    const int b   = blockIdx.x >> 5;                 // 32 blocks per batch
    const int i   = ((blockIdx.x & 31) << 8) + tid;
    const float* xb = xyz + b*3*NPTS;
    const float xi = xb[i], yi = xb[NPTS+i], zi = xb[2*NPTS+i];

    float bd[KNB]; int bj[KNB];
#pragma unroll
    for (int t = 0; t < KNB; t++) { bd[t] = 3.4e38f; bj[t] = 0; }
    float cmax = 3.4e38f;

    for (int c0 = 0; c0 < NPTS; c0 += 4096) {
        __syncthreads();
        for (int l = tid; l < 4096; l += 256) {
            sx[l] = xb[c0+l]; sy[l] = xb[NPTS+c0+l]; sz[l] = xb[2*NPTS+c0+l];
        }
        __syncthreads();
#pragma unroll 4
        for (int j = 0; j < 4096; j++) {
            float dx = sx[j]-xi, dy = sy[j]-yi, dz = sz[j]-zi;
            float d2 = fmaf(dx,dx, fmaf(dy,dy, dz*dz));
            if (d2 < cmax) {
                int am = 0; float mv = bd[0];
#pragma unroll
                for (int t = 1; t < KNB; t++) if (bd[t] > mv) { mv = bd[t]; am = t; }
#pragma unroll
                for (int t = 0; t < KNB; t++) if (t == am) { bd[t] = d2; bj[t] = c0+j; }
                cmax = bd[0];
#pragma unroll
                for (int t = 1; t < KNB; t++) cmax = fmaxf(cmax, bd[t]);
            }
        }
    }
    const int base = (b*NPTS + i)*KNB;
#pragma unroll
    for (int t = 0; t < KNB; t++) g_idx[base+t] = bj[t];
}

// =====================================================================
// Kernel 2: stage-1 conv_res (10->64) + in-block k-max -> g_h1, g_x1
// Block tile: 64 outputs x 64 positions (4 n x 16 k). 256 threads, 4x4.
// =====================================================================
#define FP 68
#define S1_SMEM_FLOATS 19704
__global__ __launch_bounds__(256) void stage1_kernel(
    const float* __restrict__ xyz,
    const float* __restrict__ wsc, const float* __restrict__ bsc,
    const float* __restrict__ wa,  const float* __restrict__ ba,
    const float* __restrict__ wb,  const float* __restrict__ bb,
    const float* __restrict__ wc,  const float* __restrict__ bc)
{
    extern __shared__ float sm[];
    float* sF   = sm;            // 10*68
    float* sWsc = sm + 680;      // 10*68
    float* sWa  = sm + 1360;     // 10*68
    float* sWb  = sm + 2040;     // 64*68
    float* sWc  = sm + 6392;     // 64*68
    float* sB   = sm + 10744;    // 4*64  (bsc, ba, bb, bc)
    float* sH   = sm + 11000;    // 64*68
    float* sH2  = sm + 15352;    // 64*68

    const int tid = threadIdx.x;
    const int tx = tid & 15, ty = tid >> 4;
    const int base = blockIdx.x << 6;
    const int b  = base >> 17;                       // N*K = 2^17
    const int n0 = (base & (NPTS*KNB - 1)) >> 4;

    // weights (transposed: [k][o], row stride FP)
    for (int l = tid; l < 640; l += 256) {
        int o = l / 10, k = l - o*10;
        sWsc[k*FP+o] = wsc[l]; sWa[k*FP+o] = wa[l];
    }
    for (int l = tid; l < 4096; l += 256) {
        int o = l >> 6, k = l & 63;
        sWb[k*FP+o] = wb[l]; sWc[k*FP+o] = wc[l];
    }
    if (tid < 64) { sB[tid]=bsc[tid]; sB[64+tid]=ba[tid]; sB[128+tid]=bb[tid]; sB[192+tid]=bc[tid]; }

    // features for 64 positions
    if (tid < 64) {
        int nl = tid >> 4;
        int kk = tid & 15;
        int n = n0 + nl;
        const float* xb = xyz + b*3*NPTS;
        int j = g_idx[(b*NPTS + n)*KNB + kk];
        float cx = xb[n], cy = xb[NPTS+n], cz = xb[2*NPTS+n];
        float nx = xb[j], ny = xb[NPTS+j], nz = xb[2*NPTS+j];
        float rx = nx-cx, ry = ny-cy, rz = nz-cz;
        float dd = sqrtf(fmaf(rx,rx, fmaf(ry,ry, rz*rz)) + 1e-12f);
        sF[0*FP+tid]=cx; sF[1*FP+tid]=cy; sF[2*FP+tid]=cz;
        sF[3*FP+tid]=nx; sF[4*FP+tid]=ny; sF[5*FP+tid]=nz;
        sF[6*FP+tid]=rx; sF[7*FP+tid]=ry; sF[8*FP+tid]=rz;
        sF[9*FP+tid]=dd;
    }
    __syncthreads();

    // GEMM1: sc and a (K=10)
    float aS[4][4]; float aA[4][4];
#pragma unroll
    for (int oo=0;oo<4;oo++)
#pragma unroll
        for (int pp=0;pp<4;pp++) { aS[oo][pp]=0.f; aA[oo][pp]=0.f; }
#pragma unroll
    for (int k = 0; k < 10; k++) {
        float4 ws = *(const float4*)(sWsc + k*FP + ty*4);
        float4 wa4= *(const float4*)(sWa  + k*FP + ty*4);
        float4 f  = *(const float4*)(sF   + k*FP + tx*4);
        float wsv[4]={ws.x,ws.y,ws.z,ws.w}, wav[4]={wa4.x,wa4.y,wa4.z,wa4.w};
        float fv[4]={f.x,f.y,f.z,f.w};
#pragma unroll
        for (int oo=0;oo<4;oo++)
#pragma unroll
            for (int pp=0;pp<4;pp++) {
                aS[oo][pp] = fmaf(wsv[oo], fv[pp], aS[oo][pp]);
                aA[oo][pp] = fmaf(wav[oo], fv[pp], aA[oo][pp]);
            }
    }
    // h = leaky(a + ba) -> sH
#pragma unroll
    for (int oo=0;oo<4;oo++) {
        float bav = sB[64 + ty*4 + oo];
        float4 hv;
        hv.x = leaky(aA[oo][0]+bav); hv.y = leaky(aA[oo][1]+bav);
        hv.z = leaky(aA[oo][2]+bav); hv.w = leaky(aA[oo][3]+bav);
        *(float4*)(sH + (ty*4+oo)*FP + tx*4) = hv;
    }
    __syncthreads();

    // GEMM2: b (K=64)
    float aB[4][4];
#pragma unroll
    for (int oo=0;oo<4;oo++)
#pragma unroll
        for (int pp=0;pp<4;pp++) aB[oo][pp]=0.f;
#pragma unroll 4
    for (int k = 0; k < 64; k++) {
        float4 w = *(const float4*)(sWb + k*FP + ty*4);
        float4 a = *(const float4*)(sH  + k*FP + tx*4);
        float wv[4]={w.x,w.y,w.z,w.w}, av[4]={a.x,a.y,a.z,a.w};
#pragma unroll
        for (int oo=0;oo<4;oo++)
#pragma unroll
            for (int pp=0;pp<4;pp++) aB[oo][pp] = fmaf(wv[oo], av[pp], aB[oo][pp]);
    }
#pragma unroll
    for (int oo=0;oo<4;oo++) {
        float bbv = sB[128 + ty*4 + oo];
        float4 hv;
        hv.x = leaky(aB[oo][0]+bbv); hv.y = leaky(aB[oo][1]+bbv);
        hv.z = leaky(aB[oo][2]+bbv); hv.w = leaky(aB[oo][3]+bbv);
        *(float4*)(sH2 + (ty*4+oo)*FP + tx*4) = hv;
    }
    __syncthreads();

    // GEMM3: c (K=64)
    float aC[4][4];
#pragma unroll
    for (int oo=0;oo<4;oo++)
#pragma unroll
        for (int pp=0;pp<4;pp++) aC[oo][pp]=0.f;
#pragma unroll 4
    for (int k = 0; k < 64; k++) {
        float4 w = *(const float4*)(sWc + k*FP + ty*4);
        float4 a = *(const float4*)(sH2 + k*FP + tx*4);
        float wv[4]={w.x,w.y,w.z,w.w}, av[4]={a.x,a.y,a.z,a.w};
#pragma unroll
        for (int oo=0;oo<4;oo++)
#pragma unroll
            for (int pp=0;pp<4;pp++) aC[oo][pp] = fmaf(wv[oo], av[pp], aC[oo][pp]);
    }

    // out = c + bc + sc + bsc ; store g_h1 [pos][c], and stage for k-max
    float outv[4][4];
#pragma unroll
    for (int oo=0;oo<4;oo++) {
        float bt = sB[192 + ty*4 + oo] + sB[ty*4 + oo];
#pragma unroll
        for (int pp=0;pp<4;pp++) outv[oo][pp] = aC[oo][pp] + aS[oo][pp] + bt;
    }
#pragma unroll
    for (int pp=0;pp<4;pp++) {
        float4 v = make_float4(outv[0][pp], outv[1][pp], outv[2][pp], outv[3][pp]);
        *(float4*)(g_h1 + (long long)(base + tx*4 + pp)*64 + ty*4) = v;
    }
#pragma unroll
    for (int oo=0;oo<4;oo++) {
        float4 v = make_float4(outv[oo][0], outv[oo][1], outv[oo][2], outv[oo][3]);
        *(float4*)(sH + (ty*4+oo)*FP + tx*4) = v;
    }
    __syncthreads();
    {
        int c = tid & 63, nl = tid >> 6;
        float m = sH[c*FP + nl*16];
#pragma unroll
        for (int kk = 1; kk < 16; kk++) m = fmaxf(m, sH[c*FP + nl*16 + kk]);
        g_x1[(long long)(b*NPTS + n0 + nl)*64 + c] = m;
    }
}

// =====================================================================
// Kernel 3: stage-2 conv_res (128-ch) + in-warp k-max -> d_out (B,128,N)
// Block tile: 128 outputs x 64 positions. 256 threads, 8x4 / 4x4 tiles.
// =====================================================================
#define AP 68
#define S2_SMEM_FLOATS 29952
__global__ __launch_bounds__(256) void stage2_kernel(
    const float* __restrict__ wsc, const float* __restrict__ bsc,
    const float* __restrict__ wa,  const float* __restrict__ ba,
    const float* __restrict__ wb,  const float* __restrict__ bb,
    const float* __restrict__ wc,  const float* __restrict__ bc,
    float* __restrict__ outp)
{
    extern __shared__ float sm[];
    float* sA = sm;            // 128*68  (act, later h2)
    float* sH = sm + 8704;     // 64*68
    float* sW = sm + 13056;    // up to 128*132

    const int tid = threadIdx.x;
    const int tx = tid & 15, ty = tid >> 4;
    const int base = blockIdx.x << 6;
    const int b  = base >> 17;
    const int n0 = (base & (NPTS*KNB - 1)) >> 4;

    // ---- load activation tile: ch 0..63 from g_h1, 64..127 from g_x1
    for (int l = tid; l < 1024; l += 256) {
        int p = l >> 4, q = l & 15;
        float4 v = *(const float4*)(g_h1 + (long long)(base+p)*64 + q*4);
        int c = q*4;
        sA[(c  )*AP+p]=v.x; sA[(c+1)*AP+p]=v.y; sA[(c+2)*AP+p]=v.z; sA[(c+3)*AP+p]=v.w;
    }
    for (int l = tid; l < 1024; l += 256) {
        int p = l >> 4, q = l & 15;
        int n = n0 + (p >> 4);
        float4 v = *(const float4*)(g_x1 + (long long)(b*NPTS + n)*64 + q*4);
        int c = 64 + q*4;
        sA[(c  )*AP+p]=v.x; sA[(c+1)*AP+p]=v.y; sA[(c+2)*AP+p]=v.z; sA[(c+3)*AP+p]=v.w;
    }
    // Wsc^T [k][o], stride 132
    for (int l = tid; l < 16384; l += 256) { int o = l>>7, k = l&127; sW[k*132+o] = wsc[l]; }
    __syncthreads();

    // ---- GEMM sc (K=128, 8x4)
    float aS[8][4];
#pragma unroll
    for (int oo=0;oo<8;oo++)
#pragma unroll
        for (int pp=0;pp<4;pp++) aS[oo][pp]=0.f;
#pragma unroll 2
    for (int k = 0; k < 128; k++) {
        float4 w0 = *(const float4*)(sW + k*132 + ty*8);
        float4 w1 = *(const float4*)(sW + k*132 + ty*8 + 4);
        float4 a  = *(const float4*)(sA + k*AP + tx*4);
        float wv[8]={w0.x,w0.y,w0.z,w0.w,w1.x,w1.y,w1.z,w1.w};
        float av[4]={a.x,a.y,a.z,a.w};
#pragma unroll
        for (int oo=0;oo<8;oo++)
#pragma unroll
            for (int pp=0;pp<4;pp++) aS[oo][pp] = fmaf(wv[oo], av[pp], aS[oo][pp]);
    }
    __syncthreads();
    // Wa^T (64 out), stride 68
    for (int l = tid; l < 8192; l += 256) { int o = l>>7, k = l&127; sW[k*68+o] = wa[l]; }
    __syncthreads();

    // ---- GEMM a (K=128, 4x4 onto 64 outputs)
    float aAc[4][4];
#pragma unroll
    for (int oo=0;oo<4;oo++)
#pragma unroll
        for (int pp=0;pp<4;pp++) aAc[oo][pp]=0.f;
#pragma unroll 2
    for (int k = 0; k < 128; k++) {
        float4 w = *(const float4*)(sW + k*68 + ty*4);
        float4 a = *(const float4*)(sA + k*AP + tx*4);
        float wv[4]={w.x,w.y,w.z,w.w}, av[4]={a.x,a.y,a.z,a.w};
#pragma unroll
        for (int oo=0;oo<4;oo++)
#pragma unroll
            for (int pp=0;pp<4;pp++) aAc[oo][pp] = fmaf(wv[oo], av[pp], aAc[oo][pp]);
    }
#pragma unroll
    for (int oo=0;oo<4;oo++) {
        float bav = __ldg(ba + ty*4 + oo);
        float4 hv;
        hv.x = leaky(aAc[oo][0]+bav); hv.y = leaky(aAc[oo][1]+bav);
        hv.z = leaky(aAc[oo][2]+bav); hv.w = leaky(aAc[oo][3]+bav);
        *(float4*)(sH + (ty*4+oo)*AP + tx*4) = hv;
    }
    __syncthreads();
    // Wb^T (128 out, 64 k), stride 132
    for (int l = tid; l < 8192; l += 256) { int o = l>>6, k = l&63; sW[k*132+o] = wb[l]; }
    __syncthreads();

    // ---- GEMM b (K=64, 8x4) ; h2 -> sA (act no longer needed)
    float aB[8][4];
#pragma unroll
    for (int oo=0;oo<8;oo++)
#pragma unroll
        for (int pp=0;pp<4;pp++) aB[oo][pp]=0.f;
#pragma unroll 4
    for (int k = 0; k < 64; k++) {
        float4 w0 = *(const float4*)(sW + k*132 + ty*8);
        float4 w1 = *(const float4*)(sW + k*132 + ty*8 + 4);
        float4 a  = *(const float4*)(sH + k*AP + tx*4);
        float wv[8]={w0.x,w0.y,w0.z,w0.w,w1.x,w1.y,w1.z,w1.w};
        float av[4]={a.x,a.y,a.z,a.w};
#pragma unroll
        for (int oo=0;oo<8;oo++)
#pragma unroll
            for (int pp=0;pp<4;pp++) aB[oo][pp] = fmaf(wv[oo], av[pp], aB[oo][pp]);
    }
#pragma unroll
    for (int oo=0;oo<8;oo++) {
        float bbv = __ldg(bb + ty*8 + oo);
        float4 hv;
        hv.x = leaky(aB[oo][0]+bbv); hv.y = leaky(aB[oo][1]+bbv);
        hv.z = leaky(aB[oo][2]+bbv); hv.w = leaky(aB[oo][3]+bbv);
        *(float4*)(sA + (ty*8+oo)*AP + tx*4) = hv;
    }
    __syncthreads();
    // Wc^T, stride 132
    for (int l = tid; l < 16384; l += 256) { int o = l>>7, k = l&127; sW[k*132+o] = wc[l]; }
    __syncthreads();

    // ---- GEMM c (K=128, 8x4)
    float aC[8][4];
#pragma unroll
    for (int oo=0;oo<8;oo++)
#pragma unroll
        for (int pp=0;pp<4;pp++) aC[oo][pp]=0.f;
#pragma unroll 2
    for (int k = 0; k < 128; k++) {
        float4 w0 = *(const float4*)(sW + k*132 + ty*8);
        float4 w1 = *(const float4*)(sW + k*132 + ty*8 + 4);
        float4 a  = *(const float4*)(sA + k*AP + tx*4);
        float wv[8]={w0.x,w0.y,w0.z,w0.w,w1.x,w1.y,w1.z,w1.w};
        float av[4]={a.x,a.y,a.z,a.w};
#pragma unroll
        for (int oo=0;oo<8;oo++)
#pragma unroll
            for (int pp=0;pp<4;pp++) aC[oo][pp] = fmaf(wv[oo], av[pp], aC[oo][pp]);
    }

    // ---- final: out = c + sc + biases ; k-max over tile (warp shuffle)
    const int nl = tx >> 2;
#pragma unroll
    for (int oo = 0; oo < 8; oo++) {
        int o = ty*8 + oo;
        float bt = __ldg(bsc + o) + __ldg(bc + o);
        float v0 = aC[oo][0] + aS[oo][0] + bt;
        float v1 = aC[oo][1] + aS[oo][1] + bt;
        float v2 = aC[oo][2] + aS[oo][2] + bt;
        float v3 = aC[oo][3] + aS[oo][3] + bt;
        float m = fmaxf(fmaxf(v0, v1), fmaxf(v2, v3));
        m = fmaxf(m, __shfl_xor_sync(0xffffffffu, m, 1));
        m = fmaxf(m, __shfl_xor_sync(0xffffffffu, m, 2));
        if ((tx & 3) == 0)
            outp[((long long)b*128 + o)*NPTS + n0 + nl] = m;
    }
}

// =====================================================================
extern "C" void kernel_launch(void* const* d_in, const int* in_sizes, int n_in,
                              void* d_out, int out_size)
{
    const float* xyz     = (const float*)d_in[0];
    const float* p1_sc_w = (const float*)d_in[1];
    const float* p1_sc_b = (const float*)d_in[2];
    const float* p1_a_w  = (const float*)d_in[3];
    const float* p1_a_b  = (const float*)d_in[4];
    const float* p1_b_w  = (const float*)d_in[5];
    const float* p1_b_b  = (const float*)d_in[6];
    const float* p1_c_w  = (const float*)d_in[7];
    const float* p1_c_b  = (const float*)d_in[8];
    const float* p2_sc_w = (const float*)d_in[9];
    const float* p2_sc_b = (const float*)d_in[10];
    const float* p2_a_w  = (const float*)d_in[11];
    const float* p2_a_b  = (const float*)d_in[12];
    const float* p2_b_w  = (const float*)d_in[13];
    const float* p2_b_b  = (const float*)d_in[14];
    const float* p2_c_w  = (const float*)d_in[15];
    const float* p2_c_b  = (const float*)d_in[16];
    float* outp = (float*)d_out;

    cudaFuncSetAttribute(stage1_kernel, cudaFuncAttributeMaxDynamicSharedMemorySize,
                         S1_SMEM_FLOATS*4);
    cudaFuncSetAttribute(stage2_kernel, cudaFuncAttributeMaxDynamicSharedMemorySize,
                         S2_SMEM_FLOATS*4);

    knn_kernel<<<BATCH*(NPTS/256), 256>>>(xyz);
    stage1_kernel<<<NPOS/64, 256, S1_SMEM_FLOATS*4>>>(
        xyz, p1_sc_w, p1_sc_b, p1_a_w, p1_a_b, p1_b_w, p1_b_b, p1_c_w, p1_c_b);
    stage2_kernel<<<NPOS/64, 256, S2_SMEM_FLOATS*4>>>(
        p2_sc_w, p2_sc_b, p2_a_w, p2_a_b, p2_b_w, p2_b_b, p2_c_w, p2_c_b, outp);
}

// round 2
// speedup vs baseline: 1.2044x; 1.2044x over previous
#include <cuda_runtime.h>
#include <math.h>

#define BATCH 4
#define NPTS  8192
#define KNB   16
#define NPOS  (BATCH*NPTS*KNB)   // 524288
#define AP    68                 // activation row stride (floats)

// -------- scratch (device global; no allocation) --------
__device__ int g_idx[BATCH*NPTS*KNB];            // 2 MB

typedef unsigned long long u64;

__device__ __forceinline__ u64 pk2(float x, float y) {
    u64 r; asm("mov.b64 %0,{%1,%2};" : "=l"(r) : "f"(x), "f"(y)); return r;
}
__device__ __forceinline__ float2 up2(u64 v) {
    float2 r; asm("mov.b64 {%0,%1},%2;" : "=f"(r.x), "=f"(r.y) : "l"(v)); return r;
}
__device__ __forceinline__ void fma2(u64& d, u64 a, u64 b) {
    asm("fma.rn.f32x2 %0,%1,%2,%0;" : "+l"(d) : "l"(a), "l"(b));
}
__device__ __forceinline__ float leaky(float v) { return v >= 0.f ? v : 0.2f*v; }

// =====================================================================
// Kernel 1: KNN — 4 threads per query, smem merge. Grid 512 x 256.
// =====================================================================
__global__ __launch_bounds__(256) void knn_kernel(const float* __restrict__ xyz)
{
    __shared__ float sx[4096], sy[4096], sz[4096];
    const int tid = threadIdx.x, qp = tid & 3, qi = tid >> 2;
    const int gq = blockIdx.x*64 + qi;
    const int b = gq >> 13, i = gq & (NPTS-1);
    const float* xb = xyz + b*3*NPTS;
    const float xi = xb[i], yi = xb[NPTS+i], zi = xb[2*NPTS+i];

    float bd[16]; int bj[16];
#pragma unroll
    for (int t = 0; t < 16; t++) { bd[t] = 3.4e38f; bj[t] = 0; }
    float cmax = 3.4e38f;

    for (int c0 = 0; c0 < NPTS; c0 += 4096) {
        __syncthreads();
        for (int l = tid; l < 1024; l += 256) {
            float4 vx = ((const float4*)(xb + c0))[l];
            float4 vy = ((const float4*)(xb + NPTS + c0))[l];
            float4 vz = ((const float4*)(xb + 2*NPTS + c0))[l];
            *(float4*)(sx + 4*l) = vx;
            *(float4*)(sy + 4*l) = vy;
            *(float4*)(sz + 4*l) = vz;
        }
        __syncthreads();
#pragma unroll 4
        for (int t = 0; t < 1024; t++) {
            int j = (t << 2) + qp;
            float dx = sx[j]-xi, dy = sy[j]-yi, dz = sz[j]-zi;
            float d2 = fmaf(dx,dx, fmaf(dy,dy, dz*dz));
            if (d2 < cmax) {
                int am = 0; float mv = bd[0];
#pragma unroll
                for (int u = 1; u < 16; u++) if (bd[u] > mv) { mv = bd[u]; am = u; }
#pragma unroll
                for (int u = 0; u < 16; u++) if (u == am) { bd[u] = d2; bj[u] = c0 + j; }
                cmax = bd[0];
#pragma unroll
                for (int u = 1; u < 16; u++) cmax = fmaxf(cmax, bd[u]);
            }
        }
    }
    __syncthreads();
    float* sD = sx; int* sJ = (int*)sy;
    {
        int bofs = qi*64 + qp*16;
#pragma unroll
        for (int t = 0; t < 16; t++) { sD[bofs+t] = bd[t]; sJ[bofs+t] = bj[t]; }
    }
    __syncthreads();
    if (tid < 64) {
        const float* D = sD + tid*64; const int* J = sJ + tid*64;
        float cd[16]; int cj[16];
#pragma unroll
        for (int t = 0; t < 16; t++) { cd[t] = D[t]; cj[t] = J[t]; }
        float cm = cd[0];
#pragma unroll
        for (int t = 1; t < 16; t++) cm = fmaxf(cm, cd[t]);
        for (int e = 16; e < 64; e++) {
            float d = D[e];
            if (d < cm) {
                int am = 0; float mv = cd[0];
#pragma unroll
                for (int u = 1; u < 16; u++) if (cd[u] > mv) { mv = cd[u]; am = u; }
                cd[am] = d; cj[am] = J[e];
                cm = cd[0];
#pragma unroll
                for (int u = 1; u < 16; u++) cm = fmaxf(cm, cd[u]);
            }
        }
        int gq2 = blockIdx.x*64 + tid;
#pragma unroll
        for (int t = 0; t < 16; t++) g_idx[gq2*16 + t] = cj[t];
    }
}

// =====================================================================
// Packed-f32x2 GEMM helpers (k-major weights, broadcast pair loads)
// =====================================================================
template<int K, int WS>
__device__ __forceinline__ void gemm8x4(const float* __restrict__ wT,
                                        const float* __restrict__ act,
                                        int ty, int tx, u64 acc[4][4])
{
#pragma unroll 4
    for (int k = 0; k < K; k++) {
        const float* wr = wT + k*WS + ty*8;
        ulonglong2 wlo = *(const ulonglong2*)wr;
        ulonglong2 whi = *(const ulonglong2*)(wr + 4);
        float4 a = *(const float4*)(act + k*AP + tx*4);
        u64 a0 = pk2(a.x,a.x), a1 = pk2(a.y,a.y), a2 = pk2(a.z,a.z), a3 = pk2(a.w,a.w);
        fma2(acc[0][0],wlo.x,a0); fma2(acc[0][1],wlo.x,a1); fma2(acc[0][2],wlo.x,a2); fma2(acc[0][3],wlo.x,a3);
        fma2(acc[1][0],wlo.y,a0); fma2(acc[1][1],wlo.y,a1); fma2(acc[1][2],wlo.y,a2); fma2(acc[1][3],wlo.y,a3);
        fma2(acc[2][0],whi.x,a0); fma2(acc[2][1],whi.x,a1); fma2(acc[2][2],whi.x,a2); fma2(acc[2][3],whi.x,a3);
        fma2(acc[3][0],whi.y,a0); fma2(acc[3][1],whi.y,a1); fma2(acc[3][2],whi.y,a2); fma2(acc[3][3],whi.y,a3);
    }
}

template<int K, int WS>
__device__ __forceinline__ void gemm4x4(const float* __restrict__ wT,
                                        const float* __restrict__ act,
                                        int ty, int tx, u64 acc[2][4])
{
#pragma unroll 4
    for (int k = 0; k < K; k++) {
        ulonglong2 w = *(const ulonglong2*)(wT + k*WS + ty*4);
        float4 a = *(const float4*)(act + k*AP + tx*4);
        u64 a0 = pk2(a.x,a.x), a1 = pk2(a.y,a.y), a2 = pk2(a.z,a.z), a3 = pk2(a.w,a.w);
        fma2(acc[0][0],w.x,a0); fma2(acc[0][1],w.x,a1); fma2(acc[0][2],w.x,a2); fma2(acc[0][3],w.x,a3);
        fma2(acc[1][0],w.y,a0); fma2(acc[1][1],w.y,a1); fma2(acc[1][2],w.y,a2); fma2(acc[1][3],w.y,a3);
    }
}

// coalesced load + k-major transpose store: src [OR o][KC k] -> dst [k][o] stride WS
template<int OR, int KC, int WS>
__device__ __forceinline__ void loadT(float* __restrict__ dst,
                                      const float* __restrict__ src, int tid)
{
    constexpr int KQ = KC/4;
#pragma unroll 2
    for (int l = tid; l < OR*KQ; l += 256) {
        int o = l / KQ; int k = (l - o*KQ) * 4;
        float4 v = ((const float4*)src)[l];
        dst[(k  )*WS + o] = v.x;
        dst[(k+1)*WS + o] = v.y;
        dst[(k+2)*WS + o] = v.z;
        dst[(k+3)*WS + o] = v.w;
    }
}

// =====================================================================
// Kernel 2: fused stage1 + stage2 per 64-position tile (4 n x 16 k)
// =====================================================================
#define SMEM_FLOATS 28152
__global__ __launch_bounds__(256,2) void fused_kernel(
    const float* __restrict__ xyz,
    const float* __restrict__ w1sc, const float* __restrict__ b1sc,
    const float* __restrict__ w1a,  const float* __restrict__ b1a,
    const float* __restrict__ w1b,  const float* __restrict__ b1b,
    const float* __restrict__ w1c,  const float* __restrict__ b1c,
    const float* __restrict__ w2sc, const float* __restrict__ b2sc,
    const float* __restrict__ w2a,  const float* __restrict__ b2a,
    const float* __restrict__ w2b,  const float* __restrict__ b2b,
    const float* __restrict__ w2c,  const float* __restrict__ b2c,
    float* __restrict__ outp)
{
    extern __shared__ float sm[];
    float* sAct = sm;             // 64*68 = 4352
    float* sH   = sm + 4352;      // 64*68 = 4352
    float* sW   = sm + 8704;      // 16896 (max 128*132)
    float* sX1  = sm + 25600;     // 64*4 = 256
    float* sF   = sm + 25856;     // 10*68 = 680
    float* sW1s = sm + 26536;     // 10*68
    float* sW1a = sm + 27216;     // 10*68
    float* sB1  = sm + 27896;     // 256

    const int tid = threadIdx.x, tx = tid & 15, ty = tid >> 4;
    const int base = blockIdx.x << 6;
    const int b  = base >> 17;
    const int n0 = (base & (NPTS*KNB - 1)) >> 4;
    const int nloc = tx >> 2, q = tx & 3;

    // ---------------- phase 0: loads ----------------
    loadT<64,64,AP>(sW,        w1b, tid);
    loadT<64,64,AP>(sW + 4352, w1c, tid);
    for (int l = tid; l < 640; l += 256) {
        int o = l/10, k = l - o*10;
        sW1s[k*AP+o] = w1sc[l]; sW1a[k*AP+o] = w1a[l];
    }
    if (tid < 64) { sB1[tid]=b1sc[tid]; sB1[64+tid]=b1a[tid]; sB1[128+tid]=b1b[tid]; sB1[192+tid]=b1c[tid]; }
    if (tid < 64) {
        int nl = tid >> 4, kk = tid & 15, n = n0 + nl;
        const float* xb = xyz + b*3*NPTS;
        int j = g_idx[(b*NPTS + n)*KNB + kk];
        float cx = xb[n], cy = xb[NPTS+n], cz = xb[2*NPTS+n];
        float nx = xb[j], ny = xb[NPTS+j], nz = xb[2*NPTS+j];
        float rx = nx-cx, ry = ny-cy, rz = nz-cz;
        float dd = sqrtf(fmaf(rx,rx, fmaf(ry,ry, rz*rz)) + 1e-12f);
        sF[0*AP+tid]=cx; sF[1*AP+tid]=cy; sF[2*AP+tid]=cz;
        sF[3*AP+tid]=nx; sF[4*AP+tid]=ny; sF[5*AP+tid]=nz;
        sF[6*AP+tid]=rx; sF[7*AP+tid]=ry; sF[8*AP+tid]=rz;
        sF[9*AP+tid]=dd;
    }
    __syncthreads();

    // ---------------- stage1 sc + a (K=10, plain FFMA) ----------------
    float aS1[4][4], aA1[4][4];
#pragma unroll
    for (int oo=0;oo<4;oo++)
#pragma unroll
        for (int pp=0;pp<4;pp++) { aS1[oo][pp]=0.f; aA1[oo][pp]=0.f; }
#pragma unroll
    for (int k = 0; k < 10; k++) {
        float4 ws = *(const float4*)(sW1s + k*AP + ty*4);
        float4 wa = *(const float4*)(sW1a + k*AP + ty*4);
        float4 f  = *(const float4*)(sF   + k*AP + tx*4);
        float wsv[4]={ws.x,ws.y,ws.z,ws.w}, wav[4]={wa.x,wa.y,wa.z,wa.w}, fv[4]={f.x,f.y,f.z,f.w};
#pragma unroll
        for (int oo=0;oo<4;oo++)
#pragma unroll
            for (int pp=0;pp<4;pp++) {
                aS1[oo][pp] = fmaf(wsv[oo], fv[pp], aS1[oo][pp]);
                aA1[oo][pp] = fmaf(wav[oo], fv[pp], aA1[oo][pp]);
            }
    }
#pragma unroll
    for (int oo=0;oo<4;oo++) {
        float bav = sB1[64 + ty*4 + oo];
        float4 hv;
        hv.x = leaky(aA1[oo][0]+bav); hv.y = leaky(aA1[oo][1]+bav);
        hv.z = leaky(aA1[oo][2]+bav); hv.w = leaky(aA1[oo][3]+bav);
        *(float4*)(sH + (ty*4+oo)*AP + tx*4) = hv;
    }
    __syncthreads();

    // ---------------- stage1 b (K=64, packed) ----------------
    {
        u64 acc[2][4] = {{0,0,0,0},{0,0,0,0}};
        gemm4x4<64,AP>(sW, sH, ty, tx, acc);
        float hv[4][4];
#pragma unroll
        for (int j=0;j<2;j++)
#pragma unroll
            for (int pp=0;pp<4;pp++) { float2 v = up2(acc[j][pp]); hv[2*j][pp]=v.x; hv[2*j+1][pp]=v.y; }
#pragma unroll
        for (int oo=0;oo<4;oo++) {
            float bbv = sB1[128 + ty*4 + oo];
            float4 o4;
            o4.x = leaky(hv[oo][0]+bbv); o4.y = leaky(hv[oo][1]+bbv);
            o4.z = leaky(hv[oo][2]+bbv); o4.w = leaky(hv[oo][3]+bbv);
            *(float4*)(sAct + (ty*4+oo)*AP + tx*4) = o4;
        }
    }
    __syncthreads();

    // ---------------- stage1 c (K=64, packed) + out1 + x1 ----------------
    float outv[4][4];
    {
        u64 acc[2][4] = {{0,0,0,0},{0,0,0,0}};
        gemm4x4<64,AP>(sW + 4352, sAct, ty, tx, acc);
#pragma unroll
        for (int j=0;j<2;j++)
#pragma unroll
            for (int pp=0;pp<4;pp++) { float2 v = up2(acc[j][pp]); outv[2*j][pp]=v.x; outv[2*j+1][pp]=v.y; }
#pragma unroll
        for (int oo=0;oo<4;oo++) {
            float bt = sB1[192 + ty*4 + oo] + sB1[ty*4 + oo];
#pragma unroll
            for (int pp=0;pp<4;pp++) outv[oo][pp] += aS1[oo][pp] + bt;
        }
    }
    __syncthreads();   // everyone done reading sAct (h2) and sW (Wc1)
    // store out1 into sAct; compute x1 via shuffles
#pragma unroll
    for (int oo=0;oo<4;oo++) {
        float4 o4 = make_float4(outv[oo][0], outv[oo][1], outv[oo][2], outv[oo][3]);
        *(float4*)(sAct + (ty*4+oo)*AP + tx*4) = o4;
        float m = fmaxf(fmaxf(outv[oo][0], outv[oo][1]), fmaxf(outv[oo][2], outv[oo][3]));
        m = fmaxf(m, __shfl_xor_sync(0xffffffffu, m, 1));
        m = fmaxf(m, __shfl_xor_sync(0xffffffffu, m, 2));
        if (q == 0) sX1[(ty*4+oo)*4 + nloc] = m;
    }
    loadT<128,128,132>(sW, w2sc, tid);
    __syncthreads();

    // ---------------- stage2 sc: K=64 main + per-n correction ----------------
    float aS[8][4];
    {
        u64 acc[4][4] = {{0,0,0,0},{0,0,0,0},{0,0,0,0},{0,0,0,0}};
        gemm8x4<64,132>(sW, sAct, ty, tx, acc);
#pragma unroll
        for (int p=0;p<4;p++)
#pragma unroll
            for (int pp=0;pp<4;pp++) { float2 v = up2(acc[p][pp]); aS[2*p][pp]=v.x; aS[2*p+1][pp]=v.y; }
        float a2[8] = {0,0,0,0,0,0,0,0};
#pragma unroll
        for (int i=0;i<16;i++) {
            int c = i*4 + q;
            float xv = sX1[c*4 + nloc];
            const float* wr = sW + (64+c)*132 + ty*8;
            float4 w0 = *(const float4*)wr, w1 = *(const float4*)(wr+4);
            a2[0]=fmaf(w0.x,xv,a2[0]); a2[1]=fmaf(w0.y,xv,a2[1]);
            a2[2]=fmaf(w0.z,xv,a2[2]); a2[3]=fmaf(w0.w,xv,a2[3]);
            a2[4]=fmaf(w1.x,xv,a2[4]); a2[5]=fmaf(w1.y,xv,a2[5]);
            a2[6]=fmaf(w1.z,xv,a2[6]); a2[7]=fmaf(w1.w,xv,a2[7]);
        }
#pragma unroll
        for (int t=0;t<8;t++) {
            a2[t] += __shfl_xor_sync(0xffffffffu, a2[t], 1);
            a2[t] += __shfl_xor_sync(0xffffffffu, a2[t], 2);
        }
#pragma unroll
        for (int oo=0;oo<8;oo++)
#pragma unroll
            for (int pp=0;pp<4;pp++) aS[oo][pp] += a2[oo];
    }
    __syncthreads();
    loadT<64,128,AP>(sW, w2a, tid);
    __syncthreads();

    // ---------------- stage2 a: K=64 main + per-n ----------------
    {
        u64 acc[2][4] = {{0,0,0,0},{0,0,0,0}};
        gemm4x4<64,AP>(sW, sAct, ty, tx, acc);
        float av[4][4];
#pragma unroll
        for (int j=0;j<2;j++)
#pragma unroll
            for (int pp=0;pp<4;pp++) { float2 v = up2(acc[j][pp]); av[2*j][pp]=v.x; av[2*j+1][pp]=v.y; }
        float a2[4] = {0,0,0,0};
#pragma unroll
        for (int i=0;i<16;i++) {
            int c = i*4 + q;
            float xv = sX1[c*4 + nloc];
            float4 w = *(const float4*)(sW + (64+c)*AP + ty*4);
            a2[0]=fmaf(w.x,xv,a2[0]); a2[1]=fmaf(w.y,xv,a2[1]);
            a2[2]=fmaf(w.z,xv,a2[2]); a2[3]=fmaf(w.w,xv,a2[3]);
        }
#pragma unroll
        for (int t=0;t<4;t++) {
            a2[t] += __shfl_xor_sync(0xffffffffu, a2[t], 1);
            a2[t] += __shfl_xor_sync(0xffffffffu, a2[t], 2);
        }
#pragma unroll
        for (int oo=0;oo<4;oo++) {
            float bav = __ldg(b2a + ty*4 + oo);
            float4 hv;
            hv.x = leaky(av[oo][0]+a2[oo]+bav); hv.y = leaky(av[oo][1]+a2[oo]+bav);
            hv.z = leaky(av[oo][2]+a2[oo]+bav); hv.w = leaky(av[oo][3]+a2[oo]+bav);
            *(float4*)(sH + (ty*4+oo)*AP + tx*4) = hv;
        }
    }
    __syncthreads();
    loadT<128,64,132>(sW, w2b, tid);
    __syncthreads();

    // ---------------- stage2 b: K=64 packed; h2 -> sAct(0-63)/sH(64-127) ----------------
    {
        u64 acc[4][4] = {{0,0,0,0},{0,0,0,0},{0,0,0,0},{0,0,0,0}};
        gemm8x4<64,132>(sW, sH, ty, tx, acc);
        float bv[8][4];
#pragma unroll
        for (int p=0;p<4;p++)
#pragma unroll
            for (int pp=0;pp<4;pp++) { float2 v = up2(acc[p][pp]); bv[2*p][pp]=v.x; bv[2*p+1][pp]=v.y; }
        __syncthreads();   // everyone done reading sH (h) and sAct
#pragma unroll
        for (int oo=0;oo<8;oo++) {
            int o = ty*8 + oo;
            float bbv = __ldg(b2b + o);
            float4 hv;
            hv.x = leaky(bv[oo][0]+bbv); hv.y = leaky(bv[oo][1]+bbv);
            hv.z = leaky(bv[oo][2]+bbv); hv.w = leaky(bv[oo][3]+bbv);
            float* dst = (o < 64) ? (sAct + o*AP) : (sH + (o-64)*AP);
            *(float4*)(dst + tx*4) = hv;
        }
    }
    loadT<128,128,132>(sW, w2c, tid);
    __syncthreads();

    // ---------------- stage2 c: K=128 packed (split halves) + epilogue ----------------
    {
        u64 acc[4][4] = {{0,0,0,0},{0,0,0,0},{0,0,0,0},{0,0,0,0}};
        gemm8x4<64,132>(sW,          sAct, ty, tx, acc);
        gemm8x4<64,132>(sW + 64*132, sH,   ty, tx, acc);
#pragma unroll
        for (int p=0;p<4;p++) {
#pragma unroll
            for (int pp=0;pp<4;pp++) {
                float2 v = up2(acc[p][pp]);
                int o0 = ty*8 + 2*p, o1 = o0 + 1;
                float bt0 = __ldg(b2sc + o0) + __ldg(b2c + o0);
                float bt1 = __ldg(b2sc + o1) + __ldg(b2c + o1);
                // reuse acc storage as final values via aS
                aS[2*p][pp]   += v.x + bt0*0.25f*4.f*0.f; // placeholder avoided below
                aS[2*p+1][pp] += v.y;
                aS[2*p][pp]   += v.x - v.x; // no-op guard
                (void)bt0; (void)bt1;
            }
        }
        // NOTE: the block above is replaced by explicit epilogue:
    }
    // explicit epilogue (recompute cleanly to avoid the placeholder above)
    // -- done inline here because aS was already modified; see store below
    {
        // aS now holds sc + (c-contrib added for even/odd o, without biases):
        // finish: add biases, reduce max over k, write output
#pragma unroll
        for (int oo=0;oo<8;oo++) {
            int o = ty*8 + oo;
            float bt = __ldg(b2sc + o) + __ldg(b2c + o);
            float v0 = aS[oo][0] + bt, v1 = aS[oo][1] + bt;
            float v2 = aS[oo][2] + bt, v3 = aS[oo][3] + bt;
            float m = fmaxf(fmaxf(v0, v1), fmaxf(v2, v3));
            m = fmaxf(m, __shfl_xor_sync(0xffffffffu, m, 1));
            m = fmaxf(m, __shfl_xor_sync(0xffffffffu, m, 2));
            if (q == 0)
                outp[((long long)b*128 + o)*NPTS + n0 + nloc] = m;
        }
    }
}

// =====================================================================
extern "C" void kernel_launch(void* const* d_in, const int* in_sizes, int n_in,
                              void* d_out, int out_size)
{
    const float* xyz     = (const float*)d_in[0];
    const float* p1_sc_w = (const float*)d_in[1];
    const float* p1_sc_b = (const float*)d_in[2];
    const float* p1_a_w  = (const float*)d_in[3];
    const float* p1_a_b  = (const float*)d_in[4];
    const float* p1_b_w  = (const float*)d_in[5];
    const float* p1_b_b  = (const float*)d_in[6];
    const float* p1_c_w  = (const float*)d_in[7];
    const float* p1_c_b  = (const float*)d_in[8];
    const float* p2_sc_w = (const float*)d_in[9];
    const float* p2_sc_b = (const float*)d_in[10];
    const float* p2_a_w  = (const float*)d_in[11];
    const float* p2_a_b  = (const float*)d_in[12];
    const float* p2_b_w  = (const float*)d_in[13];
    const float* p2_b_b  = (const float*)d_in[14];
    const float* p2_c_w  = (const float*)d_in[15];
    const float* p2_c_b  = (const float*)d_in[16];
    float* outp = (float*)d_out;

    cudaFuncSetAttribute(fused_kernel, cudaFuncAttributeMaxDynamicSharedMemorySize,
                         SMEM_FLOATS*4);

    knn_kernel<<<512, 256>>>(xyz);
    fused_kernel<<<NPOS/64, 256, SMEM_FLOATS*4>>>(
        xyz,
        p1_sc_w, p1_sc_b, p1_a_w, p1_a_b, p1_b_w, p1_b_b, p1_c_w, p1_c_b,
        p2_sc_w, p2_sc_b, p2_a_w, p2_a_b, p2_b_w, p2_b_b, p2_c_w, p2_c_b,
        outp);
}

// round 3
// speedup vs baseline: 1.2351x; 1.0255x over previous
#include <cuda_runtime.h>
#include <math.h>

#define BATCH 4
#define NPTS  8192
#define KNB   16
#define NPOS  (BATCH*NPTS*KNB)   // 524288

__device__ int g_idx[BATCH*NPTS*KNB];

typedef unsigned long long u64;

__device__ __forceinline__ u64 pk2(float x, float y) {
    u64 r; asm("mov.b64 %0,{%1,%2};" : "=l"(r) : "f"(x), "f"(y)); return r;
}
__device__ __forceinline__ float2 up2(u64 v) {
    float2 r; asm("mov.b64 {%0,%1},%2;" : "=f"(r.x), "=f"(r.y) : "l"(v)); return r;
}
__device__ __forceinline__ void fma2(u64& d, u64 a, u64 b) {
    asm("fma.rn.f32x2 %0,%1,%2,%0;" : "+l"(d) : "l"(a), "l"(b));
}
__device__ __forceinline__ float leaky(float v) { return v >= 0.f ? v : 0.2f*v; }

// =====================================================================
// Kernel 1: KNN — 4 threads per query, smem merge. Grid 512 x 256.
// =====================================================================
__global__ __launch_bounds__(256) void knn_kernel(const float* __restrict__ xyz)
{
    __shared__ float sx[4096], sy[4096], sz[4096];
    const int tid = threadIdx.x, qp = tid & 3, qi = tid >> 2;
    const int gq = blockIdx.x*64 + qi;
    const int b = gq >> 13, i = gq & (NPTS-1);
    const float* xb = xyz + b*3*NPTS;
    const float xi = xb[i], yi = xb[NPTS+i], zi = xb[2*NPTS+i];

    float bd[16]; int bj[16];
#pragma unroll
    for (int t = 0; t < 16; t++) { bd[t] = 3.4e38f; bj[t] = 0; }
    float cmax = 3.4e38f;

    for (int c0 = 0; c0 < NPTS; c0 += 4096) {
        __syncthreads();
        for (int l = tid; l < 1024; l += 256) {
            float4 vx = ((const float4*)(xb + c0))[l];
            float4 vy = ((const float4*)(xb + NPTS + c0))[l];
            float4 vz = ((const float4*)(xb + 2*NPTS + c0))[l];
            *(float4*)(sx + 4*l) = vx;
            *(float4*)(sy + 4*l) = vy;
            *(float4*)(sz + 4*l) = vz;
        }
        __syncthreads();
#pragma unroll 4
        for (int t = 0; t < 1024; t++) {
            int j = (t << 2) + qp;
            float dx = sx[j]-xi, dy = sy[j]-yi, dz = sz[j]-zi;
            float d2 = fmaf(dx,dx, fmaf(dy,dy, dz*dz));
            if (d2 < cmax) {
                int am = 0; float mv = bd[0];
#pragma unroll
                for (int u = 1; u < 16; u++) if (bd[u] > mv) { mv = bd[u]; am = u; }
#pragma unroll
                for (int u = 0; u < 16; u++) if (u == am) { bd[u] = d2; bj[u] = c0 + j; }
                cmax = bd[0];
#pragma unroll
                for (int u = 1; u < 16; u++) cmax = fmaxf(cmax, bd[u]);
            }
        }
    }
    __syncthreads();
    float* sD = sx; int* sJ = (int*)sy;
    {
        int bofs = qi*64 + qp*16;
#pragma unroll
        for (int t = 0; t < 16; t++) { sD[bofs+t] = bd[t]; sJ[bofs+t] = bj[t]; }
    }
    __syncthreads();
    if (tid < 64) {
        const float* D = sD + tid*64; const int* J = sJ + tid*64;
        float cd[16]; int cj[16];
#pragma unroll
        for (int t = 0; t < 16; t++) { cd[t] = D[t]; cj[t] = J[t]; }
        float cm = cd[0];
#pragma unroll
        for (int t = 1; t < 16; t++) cm = fmaxf(cm, cd[t]);
        for (int e = 16; e < 64; e++) {
            float d = D[e];
            if (d < cm) {
                int am = 0; float mv = cd[0];
#pragma unroll
                for (int u = 1; u < 16; u++) if (cd[u] > mv) { mv = cd[u]; am = u; }
                cd[am] = d; cj[am] = J[e];
                cm = cd[0];
#pragma unroll
                for (int u = 1; u < 16; u++) cm = fmaxf(cm, cd[u]);
            }
        }
        int gq2 = blockIdx.x*64 + tid;
#pragma unroll
        for (int t = 0; t < 16; t++) g_idx[gq2*16 + t] = cj[t];
    }
}

// =====================================================================
// smem layout (floats)
// =====================================================================
#define SA    0        // 64*68 = 4352  activation buf A
#define SB    4352     // 4352          activation buf B (out1 persists)
#define SC    8704     // 4352          activation buf C
#define SWB   13056    // 8704          weight buffer (k-major)
#define SF    21760    // 10*68 = 680   stage1 features
#define SW1S  22440    // 680
#define SW1A  23120    // 680
#define SX1   23800    // 64*4 = 256
#define SBIAS 24056    // 256
#define SMEM_FLOATS 24312   // 97248 bytes -> 2 CTAs/SM

// o-fast transposed weight load: src row-major [OR][KFULL], copy cols
// [koff,koff+KLEN) into dst[k][o] (stride WS). Conflict-free STS
// (consecutive lanes -> consecutive o -> consecutive banks).
template<int OR, int KFULL, int KLEN, int WS>
__device__ __forceinline__ void loadTW(float* __restrict__ dst,
                                       const float* __restrict__ src,
                                       int koff, int tid)
{
    constexpr int ITERS = OR*(KLEN/4)/128;
#pragma unroll
    for (int it = 0; it < ITERS; it++) {
        int l = it*128 + tid;
        int o  = l & (OR-1);
        int k4 = l >> (OR == 128 ? 7 : 6);
        float4 v = *(const float4*)(src + o*KFULL + koff + 4*k4);
        int k = 4*k4;
        dst[(k  )*WS + o] = v.x;
        dst[(k+1)*WS + o] = v.y;
        dst[(k+2)*WS + o] = v.z;
        dst[(k+3)*WS + o] = v.w;
    }
}

// 8 out x 8 pos packed GEMM, K=64. w: [k][o] stride 132. a: [k][pos] stride 68.
__device__ __forceinline__ void gemm8x8(const float* __restrict__ w,
                                        const float* __restrict__ a,
                                        int og, int pg, u64 acc[8][4])
{
#pragma unroll 4
    for (int k = 0; k < 64; k++) {
        const float* wr = w + k*132 + og*8;
        float4 w0 = *(const float4*)wr;
        float4 w1 = *(const float4*)(wr+4);
        ulonglong2 a01 = *(const ulonglong2*)(a + k*68 + pg*8);
        ulonglong2 a23 = *(const ulonglong2*)(a + k*68 + pg*8 + 4);
        u64 av[4] = {a01.x, a01.y, a23.x, a23.y};
        u64 ws[8] = {pk2(w0.x,w0.x), pk2(w0.y,w0.y), pk2(w0.z,w0.z), pk2(w0.w,w0.w),
                     pk2(w1.x,w1.x), pk2(w1.y,w1.y), pk2(w1.z,w1.z), pk2(w1.w,w1.w)};
#pragma unroll
        for (int o = 0; o < 8; o++)
#pragma unroll
            for (int j = 0; j < 4; j++) fma2(acc[o][j], ws[o], av[j]);
    }
}

// 4 out x 8 pos packed GEMM. w: [k][o] stride 68.
template<int K>
__device__ __forceinline__ void gemm4x8(const float* __restrict__ w,
                                        const float* __restrict__ a,
                                        int og4, int pg, u64 acc[4][4])
{
#pragma unroll 4
    for (int k = 0; k < K; k++) {
        float4 w0 = *(const float4*)(w + k*68 + og4*4);
        ulonglong2 a01 = *(const ulonglong2*)(a + k*68 + pg*8);
        ulonglong2 a23 = *(const ulonglong2*)(a + k*68 + pg*8 + 4);
        u64 av[4] = {a01.x, a01.y, a23.x, a23.y};
        u64 ws[4] = {pk2(w0.x,w0.x), pk2(w0.y,w0.y), pk2(w0.z,w0.z), pk2(w0.w,w0.w)};
#pragma unroll
        for (int o = 0; o < 4; o++)
#pragma unroll
            for (int j = 0; j < 4; j++) fma2(acc[o][j], ws[o], av[j]);
    }
}

// =====================================================================
// Fused kernel: one 64-pos tile per 128-thread block
// =====================================================================
__global__ void __launch_bounds__(128) fused_kernel(
    const float* __restrict__ xyz,
    const float* __restrict__ w1sc, const float* __restrict__ b1sc,
    const float* __restrict__ w1a,  const float* __restrict__ b1a,
    const float* __restrict__ w1b,  const float* __restrict__ b1b,
    const float* __restrict__ w1c,  const float* __restrict__ b1c,
    const float* __restrict__ w2sc, const float* __restrict__ b2sc,
    const float* __restrict__ w2a,  const float* __restrict__ b2a,
    const float* __restrict__ w2b,  const float* __restrict__ b2b,
    const float* __restrict__ w2c,  const float* __restrict__ b2c,
    float* __restrict__ outp)
{
    extern __shared__ float sm[];
    const int tid = threadIdx.x;
    const int pg = tid & 7, og = tid >> 3;   // og 0..15
    const int base = blockIdx.x << 6;
    const int b  = base >> 17;
    const int n0 = (base & (NPTS*KNB - 1)) >> 4;
    const int nl = pg >> 1;                  // local n 0..3 (thread's 8 pos share one n)

    // ---- P0: features, stage1 small weights, biases, sW <- w1b ----
    loadTW<64,64,64,68>(sm + SWB, w1b, 0, tid);
    for (int l = tid; l < 640; l += 128) {
        int o = l/10, k = l - o*10;
        sm[SW1S + k*68 + o] = w1sc[l];
        sm[SW1A + k*68 + o] = w1a[l];
    }
    if (tid < 64) {
        sm[SBIAS+tid] = b1sc[tid]; sm[SBIAS+64+tid] = b1a[tid];
        sm[SBIAS+128+tid] = b1b[tid]; sm[SBIAS+192+tid] = b1c[tid];
    }
    if (tid < 64) {
        int nn = n0 + (tid >> 4), kk = tid & 15;
        const float* xb = xyz + b*3*NPTS;
        int j = g_idx[(b*NPTS + nn)*KNB + kk];
        float cx = xb[nn], cy = xb[NPTS+nn], cz = xb[2*NPTS+nn];
        float nx = xb[j],  ny = xb[NPTS+j],  nz = xb[2*NPTS+j];
        float rx = nx-cx, ry = ny-cy, rz = nz-cz;
        float dd = sqrtf(fmaf(rx,rx, fmaf(ry,ry, rz*rz)) + 1e-12f);
        sm[SF+0*68+tid]=cx; sm[SF+1*68+tid]=cy; sm[SF+2*68+tid]=cz;
        sm[SF+3*68+tid]=nx; sm[SF+4*68+tid]=ny; sm[SF+5*68+tid]=nz;
        sm[SF+6*68+tid]=rx; sm[SF+7*68+tid]=ry; sm[SF+8*68+tid]=rz;
        sm[SF+9*68+tid]=dd;
    }
    __syncthreads();

    u64 acc[8][4];
    u64 aS1[4][4];

    // ---- P1: stage1 sc + a (K=10, dual 4x8) ; h -> sA ----
    {
#pragma unroll
        for (int o=0;o<4;o++)
#pragma unroll
            for (int j=0;j<4;j++) { aS1[o][j]=0ull; acc[o][j]=0ull; }
#pragma unroll
        for (int k = 0; k < 10; k++) {
            float4 ws = *(const float4*)(sm + SW1S + k*68 + og*4);
            float4 wa = *(const float4*)(sm + SW1A + k*68 + og*4);
            ulonglong2 a01 = *(const ulonglong2*)(sm + SF + k*68 + pg*8);
            ulonglong2 a23 = *(const ulonglong2*)(sm + SF + k*68 + pg*8 + 4);
            u64 av[4] = {a01.x, a01.y, a23.x, a23.y};
            u64 wsv[4] = {pk2(ws.x,ws.x), pk2(ws.y,ws.y), pk2(ws.z,ws.z), pk2(ws.w,ws.w)};
            u64 wav[4] = {pk2(wa.x,wa.x), pk2(wa.y,wa.y), pk2(wa.z,wa.z), pk2(wa.w,wa.w)};
#pragma unroll
            for (int o=0;o<4;o++)
#pragma unroll
                for (int j=0;j<4;j++) { fma2(aS1[o][j], wsv[o], av[j]); fma2(acc[o][j], wav[o], av[j]); }
        }
#pragma unroll
        for (int o=0;o<4;o++) {
            float bav = sm[SBIAS + 64 + og*4 + o];
#pragma unroll
            for (int j=0;j<4;j++) {
                float2 v = up2(acc[o][j]);
                *(float2*)(sm + SA + (og*4+o)*68 + pg*8 + 2*j) =
                    make_float2(leaky(v.x+bav), leaky(v.y+bav));
            }
        }
    }
    __syncthreads();

    // ---- P3: stage1 b (K=64, 4x8) ; h2 -> sC ----
    {
#pragma unroll
        for (int o=0;o<4;o++)
#pragma unroll
            for (int j=0;j<4;j++) acc[o][j]=0ull;
        gemm4x8<64>(sm + SWB, sm + SA, og, pg, (u64(*)[4])acc);
#pragma unroll
        for (int o=0;o<4;o++) {
            float bbv = sm[SBIAS + 128 + og*4 + o];
#pragma unroll
            for (int j=0;j<4;j++) {
                float2 v = up2(acc[o][j]);
                *(float2*)(sm + SC + (og*4+o)*68 + pg*8 + 2*j) =
                    make_float2(leaky(v.x+bbv), leaky(v.y+bbv));
            }
        }
    }
    __syncthreads();
    loadTW<64,64,64,68>(sm + SWB, w1c, 0, tid);
    __syncthreads();

    // ---- P5: stage1 c (K=64, 4x8) ; out1 -> sB ; x1 -> sX1 ----
    {
#pragma unroll
        for (int o=0;o<4;o++)
#pragma unroll
            for (int j=0;j<4;j++) acc[o][j]=0ull;
        gemm4x8<64>(sm + SWB, sm + SC, og, pg, (u64(*)[4])acc);
#pragma unroll
        for (int o=0;o<4;o++) {
            float bt = sm[SBIAS + 192 + og*4 + o] + sm[SBIAS + og*4 + o];
            float vv[8];
#pragma unroll
            for (int j=0;j<4;j++) {
                float2 s = up2(aS1[o][j]);
                float2 v = up2(acc[o][j]);
                vv[2*j]   = v.x + s.x + bt;
                vv[2*j+1] = v.y + s.y + bt;
                *(float2*)(sm + SB + (og*4+o)*68 + pg*8 + 2*j) = make_float2(vv[2*j], vv[2*j+1]);
            }
            float m = vv[0];
#pragma unroll
            for (int t=1;t<8;t++) m = fmaxf(m, vv[t]);
            m = fmaxf(m, __shfl_xor_sync(0xffffffffu, m, 1));
            if ((pg & 1) == 0) sm[SX1 + (og*4+o)*4 + nl] = m;
        }
    }
    __syncthreads();
    loadTW<64,128,64,68>(sm + SWB,        w2a, 0,  tid);   // main K half
    loadTW<64,128,64,68>(sm + SWB + 4352, w2a, 64, tid);   // x1 half
    __syncthreads();

    // ---- P7: stage2 a (K=64 main + x1 corr, 4x8) ; h -> sA ----
    {
#pragma unroll
        for (int o=0;o<4;o++)
#pragma unroll
            for (int j=0;j<4;j++) acc[o][j]=0ull;
        gemm4x8<64>(sm + SWB, sm + SB, og, pg, (u64(*)[4])acc);
        float cr[4] = {0,0,0,0};
#pragma unroll 4
        for (int c = 0; c < 64; c++) {
            float4 w = *(const float4*)(sm + SWB + 4352 + c*68 + og*4);
            float xv = sm[SX1 + c*4 + nl];
            cr[0]=fmaf(w.x,xv,cr[0]); cr[1]=fmaf(w.y,xv,cr[1]);
            cr[2]=fmaf(w.z,xv,cr[2]); cr[3]=fmaf(w.w,xv,cr[3]);
        }
#pragma unroll
        for (int o=0;o<4;o++) {
            float bav = __ldg(b2a + og*4 + o) + cr[o];
#pragma unroll
            for (int j=0;j<4;j++) {
                float2 v = up2(acc[o][j]);
                *(float2*)(sm + SA + (og*4+o)*68 + pg*8 + 2*j) =
                    make_float2(leaky(v.x+bav), leaky(v.y+bav));
            }
        }
    }
    __syncthreads();
    loadTW<128,64,64,132>(sm + SWB, w2b, 0, tid);
    __syncthreads();

    // ---- P9: stage2 b (K=64, 8x8) ; h2 -> sA (ch<64) / sC (ch>=64) ----
    {
#pragma unroll
        for (int o=0;o<8;o++)
#pragma unroll
            for (int j=0;j<4;j++) acc[o][j]=0ull;
        gemm8x8(sm + SWB, sm + SA, og, pg, acc);
        __syncthreads();   // all reads of sA/sW done before overwrite
#pragma unroll
        for (int o=0;o<8;o++) {
            int oc = og*8 + o;
            float bbv = __ldg(b2b + oc);
            float* dst = sm + ((oc < 64) ? (SA + oc*68) : (SC + (oc-64)*68));
#pragma unroll
            for (int j=0;j<4;j++) {
                float2 v = up2(acc[o][j]);
                *(float2*)(dst + pg*8 + 2*j) = make_float2(leaky(v.x+bbv), leaky(v.y+bbv));
            }
        }
        loadTW<128,128,64,132>(sm + SWB, w2c, 0, tid);
    }
    __syncthreads();

    // ---- P11..P15: c (two K halves) + sc main, one accumulator ----
#pragma unroll
    for (int o=0;o<8;o++)
#pragma unroll
        for (int j=0;j<4;j++) acc[o][j]=0ull;
    gemm8x8(sm + SWB, sm + SA, og, pg, acc);      // c, k=0..63 (h2 lo)
    __syncthreads();
    loadTW<128,128,64,132>(sm + SWB, w2c, 64, tid);
    __syncthreads();
    gemm8x8(sm + SWB, sm + SC, og, pg, acc);      // c, k=64..127 (h2 hi)
    __syncthreads();
    loadTW<128,128,64,132>(sm + SWB, w2sc, 0, tid);
    __syncthreads();
    gemm8x8(sm + SWB, sm + SB, og, pg, acc);      // sc, k=0..63 (out1)
    __syncthreads();
    loadTW<128,128,64,132>(sm + SWB, w2sc, 64, tid);
    __syncthreads();

    // ---- P17: sc x1-corr + epilogue (max over k, write out) ----
    {
        u64 cr[4] = {0,0,0,0};
#pragma unroll 4
        for (int c = 0; c < 64; c++) {
            const float* wr = sm + SWB + c*132 + og*8;
            ulonglong2 wlo = *(const ulonglong2*)wr;
            ulonglong2 whi = *(const ulonglong2*)(wr+4);
            float xv = sm[SX1 + c*4 + nl];
            u64 xs = pk2(xv, xv);
            fma2(cr[0], wlo.x, xs); fma2(cr[1], wlo.y, xs);
            fma2(cr[2], whi.x, xs); fma2(cr[3], whi.y, xs);
        }
        float crf[8];
#pragma unroll
        for (int j=0;j<4;j++) { float2 v = up2(cr[j]); crf[2*j]=v.x; crf[2*j+1]=v.y; }
#pragma unroll
        for (int o=0;o<8;o++) {
            int oc = og*8 + o;
            float bt = __ldg(b2sc + oc) + __ldg(b2c + oc) + crf[o];
            float2 v0 = up2(acc[o][0]), v1 = up2(acc[o][1]);
            float2 v2 = up2(acc[o][2]), v3 = up2(acc[o][3]);
            float m = fmaxf(fmaxf(fmaxf(v0.x,v0.y), fmaxf(v1.x,v1.y)),
                            fmaxf(fmaxf(v2.x,v2.y), fmaxf(v3.x,v3.y))) + bt;
            m = fmaxf(m, __shfl_xor_sync(0xffffffffu, m, 1));
            if ((pg & 1) == 0)
                outp[((long long)b*128 + oc)*NPTS + n0 + nl] = m;
        }
    }
}

// =====================================================================
extern "C" void kernel_launch(void* const* d_in, const int* in_sizes, int n_in,
                              void* d_out, int out_size)
{
    const float* xyz     = (const float*)d_in[0];
    const float* p1_sc_w = (const float*)d_in[1];
    const float* p1_sc_b = (const float*)d_in[2];
    const float* p1_a_w  = (const float*)d_in[3];
    const float* p1_a_b  = (const float*)d_in[4];
    const float* p1_b_w  = (const float*)d_in[5];
    const float* p1_b_b  = (const float*)d_in[6];
    const float* p1_c_w  = (const float*)d_in[7];
    const float* p1_c_b  = (const float*)d_in[8];
    const float* p2_sc_w = (const float*)d_in[9];
    const float* p2_sc_b = (const float*)d_in[10];
    const float* p2_a_w  = (const float*)d_in[11];
    const float* p2_a_b  = (const float*)d_in[12];
    const float* p2_b_w  = (const float*)d_in[13];
    const float* p2_b_b  = (const float*)d_in[14];
    const float* p2_c_w  = (const float*)d_in[15];
    const float* p2_c_b  = (const float*)d_in[16];
    float* outp = (float*)d_out;

    cudaFuncSetAttribute(fused_kernel, cudaFuncAttributeMaxDynamicSharedMemorySize,
                         SMEM_FLOATS*4);

    knn_kernel<<<512, 256>>>(xyz);
    fused_kernel<<<NPOS/64, 128, SMEM_FLOATS*4>>>(
        xyz,
        p1_sc_w, p1_sc_b, p1_a_w, p1_a_b, p1_b_w, p1_b_b, p1_c_w, p1_c_b,
        p2_sc_w, p2_sc_b, p2_a_w, p2_a_b, p2_b_w, p2_b_b, p2_c_w, p2_c_b,
        outp);
}

// round 4
// speedup vs baseline: 1.5160x; 1.2274x over previous
#include <cuda_runtime.h>
#include <math.h>

#define BATCH 4
#define NPTS  8192
#define KNB   16
#define NPOS  (BATCH*NPTS*KNB)   // 524288
#define NQ    (BATCH*NPTS)       // 32768

__device__ int   g_idx[NQ*KNB];
__device__ float g_pd[NQ*32];
__device__ int   g_pj[NQ*32];

typedef unsigned long long u64;

__device__ __forceinline__ u64 pk2(float x, float y) {
    u64 r; asm("mov.b64 %0,{%1,%2};" : "=l"(r) : "f"(x), "f"(y)); return r;
}
__device__ __forceinline__ float2 up2(u64 v) {
    float2 r; asm("mov.b64 {%0,%1},%2;" : "=f"(r.x), "=f"(r.y) : "l"(v)); return r;
}
__device__ __forceinline__ void fma2(u64& d, u64 a, u64 b) {
    asm("fma.rn.f32x2 %0,%1,%2,%0;" : "+l"(d) : "l"(a), "l"(b));
}
__device__ __forceinline__ float leaky(float v) { return v >= 0.f ? v : 0.2f*v; }

// =====================================================================
// KNN part 1: 1 thread/query, half the candidates. 512 blocks x 128.
// =====================================================================
__global__ __launch_bounds__(128) void knn_part(const float* __restrict__ xyz)
{
    __shared__ float sx[4096], sy[4096], sz[4096];
    const int tid  = threadIdx.x;
    const int half = blockIdx.x & 1;
    const int qb   = (blockIdx.x >> 1) & 63;
    const int b    = blockIdx.x >> 7;
    const int i    = qb*128 + tid;
    const float* xb = xyz + b*3*NPTS;
    const float xi = xb[i], yi = xb[NPTS+i], zi = xb[2*NPTS+i];

    const int c0 = half*4096;
    for (int l = tid; l < 1024; l += 128) {
        float4 vx = ((const float4*)(xb + c0))[l];
        float4 vy = ((const float4*)(xb + NPTS + c0))[l];
        float4 vz = ((const float4*)(xb + 2*NPTS + c0))[l];
        *(float4*)(sx + 4*l) = vx;
        *(float4*)(sy + 4*l) = vy;
        *(float4*)(sz + 4*l) = vz;
    }
    __syncthreads();

    float bd[16]; int bj[16];
#pragma unroll
    for (int t = 0; t < 16; t++) { bd[t] = 3.4e38f; bj[t] = 0; }
    float cmax = 3.4e38f;

#pragma unroll 4
    for (int j = 0; j < 4096; j++) {
        float dx = sx[j]-xi, dy = sy[j]-yi, dz = sz[j]-zi;
        float d2 = fmaf(dx,dx, fmaf(dy,dy, dz*dz));
        if (d2 < cmax) {
            int am = 0; float mv = bd[0];
#pragma unroll
            for (int u = 1; u < 16; u++) if (bd[u] > mv) { mv = bd[u]; am = u; }
#pragma unroll
            for (int u = 0; u < 16; u++) if (u == am) { bd[u] = d2; bj[u] = c0 + j; }
            cmax = bd[0];
#pragma unroll
            for (int u = 1; u < 16; u++) cmax = fmaxf(cmax, bd[u]);
        }
    }
    const int qg = b*NPTS + i;
    const int base = qg*32 + half*16;
#pragma unroll
    for (int t = 0; t < 16; t++) { g_pd[base+t] = bd[t]; g_pj[base+t] = bj[t]; }
}

// =====================================================================
// KNN part 2: merge two 16-lists per query -> g_idx
// =====================================================================
__global__ __launch_bounds__(256) void knn_merge()
{
    const int q = blockIdx.x*256 + threadIdx.x;
    const float* D = g_pd + q*32;
    const int*   J = g_pj + q*32;
    float bd[16]; int bj[16];
#pragma unroll
    for (int t = 0; t < 16; t++) { bd[t] = D[t]; bj[t] = J[t]; }
    float cmax = bd[0];
#pragma unroll
    for (int t = 1; t < 16; t++) cmax = fmaxf(cmax, bd[t]);
    for (int e = 16; e < 32; e++) {
        float d = D[e];
        if (d < cmax) {
            int am = 0; float mv = bd[0];
#pragma unroll
            for (int u = 1; u < 16; u++) if (bd[u] > mv) { mv = bd[u]; am = u; }
            bd[am] = d; bj[am] = J[e];
            cmax = bd[0];
#pragma unroll
            for (int u = 1; u < 16; u++) cmax = fmaxf(cmax, bd[u]);
        }
    }
#pragma unroll
    for (int t = 0; t < 16; t++) g_idx[q*16+t] = bj[t];
}

// =====================================================================
// smem layout (floats)
// =====================================================================
#define SA    0        // 4352  act buf A
#define SB    4352     // 4352  act buf B (sc / out1)
#define SC    8704     // 4352  act buf C (stage1 scratch, then h2)
#define SWB   13056    // 4352  weight buffer (k-major)
#define SX1   17408    // 256
#define SBIAS 17664    // 256
#define SMEM_FLOATS 17920   // 71680 B -> 3 CTAs/SM

// o-fast transposed weight load: src row-major [OR][KFULL], cols [koff,koff+KLEN)
// -> dst[k][o] (stride WS), conflict-free STS.
template<int OR, int KFULL, int KLEN, int WS>
__device__ __forceinline__ void loadTW(float* __restrict__ dst,
                                       const float* __restrict__ src,
                                       int koff, int tid)
{
    constexpr int ITERS = OR*(KLEN/4)/128;
#pragma unroll
    for (int it = 0; it < ITERS; it++) {
        int l = it*128 + tid;
        int o  = l & (OR-1);
        int k4 = l >> (OR == 128 ? 7 : 6);
        float4 v = *(const float4*)(src + o*KFULL + koff + 4*k4);
        int k = 4*k4;
        dst[(k  )*WS + o] = v.x;
        dst[(k+1)*WS + o] = v.y;
        dst[(k+2)*WS + o] = v.z;
        dst[(k+3)*WS + o] = v.w;
    }
}

// 16 out (8 f32x2 pairs) x 4 pos. w: [k][o] stride 132. a: [k][pos] stride 68.
template<int KS>
__device__ __forceinline__ void gemm16(const float* __restrict__ w,
                                       const float* __restrict__ a,
                                       int og, int pg, u64 acc[8][4])
{
#pragma unroll 4
    for (int k = 0; k < KS; k++) {
        const float* wr = w + k*132 + og*16;
        ulonglong2 w01 = *(const ulonglong2*)wr;
        ulonglong2 w23 = *(const ulonglong2*)(wr+4);
        ulonglong2 w45 = *(const ulonglong2*)(wr+8);
        ulonglong2 w67 = *(const ulonglong2*)(wr+12);
        u64 wp[8] = {w01.x,w01.y,w23.x,w23.y,w45.x,w45.y,w67.x,w67.y};
        float4 av = *(const float4*)(a + k*68 + pg*4);
        u64 as[4] = {pk2(av.x,av.x), pk2(av.y,av.y), pk2(av.z,av.z), pk2(av.w,av.w)};
#pragma unroll
        for (int op = 0; op < 8; op++)
#pragma unroll
            for (int p = 0; p < 4; p++) fma2(acc[op][p], wp[op], as[p]);
    }
}

// 8 out (4 pairs) x 4 pos. w: [k][o] stride 68.
template<int KS>
__device__ __forceinline__ void gemm8(const float* __restrict__ w,
                                      const float* __restrict__ a,
                                      int og, int pg, u64 acc[4][4])
{
#pragma unroll 4
    for (int k = 0; k < KS; k++) {
        const float* wr = w + k*68 + og*8;
        ulonglong2 w01 = *(const ulonglong2*)wr;
        ulonglong2 w23 = *(const ulonglong2*)(wr+4);
        u64 wp[4] = {w01.x,w01.y,w23.x,w23.y};
        float4 av = *(const float4*)(a + k*68 + pg*4);
        u64 as[4] = {pk2(av.x,av.x), pk2(av.y,av.y), pk2(av.z,av.z), pk2(av.w,av.w)};
#pragma unroll
        for (int op = 0; op < 4; op++)
#pragma unroll
            for (int p = 0; p < 4; p++) fma2(acc[op][p], wp[op], as[p]);
    }
}

// =====================================================================
// Fused kernel: one 64-pos tile per 128-thread block, 3 CTAs/SM
// =====================================================================
__global__ void __launch_bounds__(128,3) fused_kernel(
    const float* __restrict__ xyz,
    const float* __restrict__ w1sc, const float* __restrict__ b1sc,
    const float* __restrict__ w1a,  const float* __restrict__ b1a,
    const float* __restrict__ w1b,  const float* __restrict__ b1b,
    const float* __restrict__ w1c,  const float* __restrict__ b1c,
    const float* __restrict__ w2sc, const float* __restrict__ b2sc,
    const float* __restrict__ w2a,  const float* __restrict__ b2a,
    const float* __restrict__ w2b,  const float* __restrict__ b2b,
    const float* __restrict__ w2c,  const float* __restrict__ b2c,
    float* __restrict__ outp)
{
    extern __shared__ float sm[];
    const int tid = threadIdx.x;
    const int pg = tid & 15, og = tid >> 4;   // og 0..7, pg 0..15
    const int base = blockIdx.x << 6;
    const int b  = base >> 17;
    const int n0 = (base & (NPTS*KNB - 1)) >> 4;
    const int nl = pg >> 2;                   // thread's 4 pos share n = n0+nl

    // ---- P0: w1b -> SWB ; feats + small weights into SC ; biases ----
    loadTW<64,64,64,68>(sm + SWB, w1b, 0, tid);
    for (int l = tid; l < 640; l += 128) {
        int o = l/10, k = l - o*10;
        sm[SC + 680  + k*68 + o] = w1sc[l];
        sm[SC + 1360 + k*68 + o] = w1a[l];
    }
    if (tid < 64) {
        sm[SBIAS+tid] = b1sc[tid]; sm[SBIAS+64+tid] = b1a[tid];
        sm[SBIAS+128+tid] = b1b[tid]; sm[SBIAS+192+tid] = b1c[tid];
    }
    if (tid < 64) {
        int nn = n0 + (tid >> 4), kk = tid & 15; (void)kk;
        const float* xb = xyz + b*3*NPTS;
        int j = g_idx[(b*NPTS + nn)*KNB + (tid & 15)];
        float cx = xb[nn], cy = xb[NPTS+nn], cz = xb[2*NPTS+nn];
        float nx = xb[j],  ny = xb[NPTS+j],  nz = xb[2*NPTS+j];
        float rx = nx-cx, ry = ny-cy, rz = nz-cz;
        float dd = sqrtf(fmaf(rx,rx, fmaf(ry,ry, rz*rz)) + 1e-12f);
        sm[SC+0*68+tid]=cx; sm[SC+1*68+tid]=cy; sm[SC+2*68+tid]=cz;
        sm[SC+3*68+tid]=nx; sm[SC+4*68+tid]=ny; sm[SC+5*68+tid]=nz;
        sm[SC+6*68+tid]=rx; sm[SC+7*68+tid]=ry; sm[SC+8*68+tid]=rz;
        sm[SC+9*68+tid]=dd;
    }
    __syncthreads();

    // ---- P1: stage1 sc + a (K=10, dual 8x4) ; h->SA ; sc->SB ----
    {
        u64 accS[4][4], accA[4][4];
#pragma unroll
        for (int op=0;op<4;op++)
#pragma unroll
            for (int p=0;p<4;p++) { accS[op][p]=0ull; accA[op][p]=0ull; }
#pragma unroll
        for (int k = 0; k < 10; k++) {
            const float* wsr = sm + SC + 680  + k*68 + og*8;
            const float* war = sm + SC + 1360 + k*68 + og*8;
            ulonglong2 ws01 = *(const ulonglong2*)wsr;
            ulonglong2 ws23 = *(const ulonglong2*)(wsr+4);
            ulonglong2 wa01 = *(const ulonglong2*)war;
            ulonglong2 wa23 = *(const ulonglong2*)(war+4);
            u64 wsp[4] = {ws01.x,ws01.y,ws23.x,ws23.y};
            u64 wap[4] = {wa01.x,wa01.y,wa23.x,wa23.y};
            float4 av = *(const float4*)(sm + SC + k*68 + pg*4);
            u64 as[4] = {pk2(av.x,av.x), pk2(av.y,av.y), pk2(av.z,av.z), pk2(av.w,av.w)};
#pragma unroll
            for (int op=0;op<4;op++)
#pragma unroll
                for (int p=0;p<4;p++) { fma2(accS[op][p], wsp[op], as[p]); fma2(accA[op][p], wap[op], as[p]); }
        }
#pragma unroll
        for (int op=0;op<4;op++) {
            int o0 = og*8 + 2*op;
            float ba0 = sm[SBIAS+64+o0], ba1 = sm[SBIAS+64+o0+1];
#pragma unroll
            for (int p=0;p<4;p++) {
                float2 va = up2(accA[op][p]);
                sm[SA + (o0  )*68 + pg*4 + p] = leaky(va.x + ba0);
                sm[SA + (o0+1)*68 + pg*4 + p] = leaky(va.y + ba1);
                float2 vs = up2(accS[op][p]);
                sm[SB + (o0  )*68 + pg*4 + p] = vs.x;
                sm[SB + (o0+1)*68 + pg*4 + p] = vs.y;
            }
        }
    }
    __syncthreads();

    // ---- P3: stage1 b (K=64) ; h2 -> SC ----
    {
        u64 acc[4][4];
#pragma unroll
        for (int op=0;op<4;op++)
#pragma unroll
            for (int p=0;p<4;p++) acc[op][p]=0ull;
        gemm8<64>(sm + SWB, sm + SA, og, pg, acc);
#pragma unroll
        for (int op=0;op<4;op++) {
            int o0 = og*8 + 2*op;
            float b0 = sm[SBIAS+128+o0], b1 = sm[SBIAS+128+o0+1];
#pragma unroll
            for (int p=0;p<4;p++) {
                float2 v = up2(acc[op][p]);
                sm[SC + (o0  )*68 + pg*4 + p] = leaky(v.x + b0);
                sm[SC + (o0+1)*68 + pg*4 + p] = leaky(v.y + b1);
            }
        }
    }
    __syncthreads();
    loadTW<64,64,64,68>(sm + SWB, w1c, 0, tid);
    __syncthreads();

    // ---- P5: stage1 c (K=64) ; out1 = c + sc(SB) + biases -> SB ; x1 ----
    {
        u64 acc[4][4];
#pragma unroll
        for (int op=0;op<4;op++)
#pragma unroll
            for (int p=0;p<4;p++) acc[op][p]=0ull;
        gemm8<64>(sm + SWB, sm + SC, og, pg, acc);
#pragma unroll
        for (int op=0;op<4;op++) {
            int o0 = og*8 + 2*op;
            float bt0 = sm[SBIAS+192+o0] + sm[SBIAS+o0];
            float bt1 = sm[SBIAS+192+o0+1] + sm[SBIAS+o0+1];
            float v0m = -3.4e38f, v1m = -3.4e38f;
#pragma unroll
            for (int p=0;p<4;p++) {
                float2 v = up2(acc[op][p]);
                float o0v = v.x + sm[SB + (o0  )*68 + pg*4 + p] + bt0;
                float o1v = v.y + sm[SB + (o0+1)*68 + pg*4 + p] + bt1;
                sm[SB + (o0  )*68 + pg*4 + p] = o0v;
                sm[SB + (o0+1)*68 + pg*4 + p] = o1v;
                v0m = fmaxf(v0m, o0v); v1m = fmaxf(v1m, o1v);
            }
            v0m = fmaxf(v0m, __shfl_xor_sync(0xffffffffu, v0m, 1));
            v0m = fmaxf(v0m, __shfl_xor_sync(0xffffffffu, v0m, 2));
            v1m = fmaxf(v1m, __shfl_xor_sync(0xffffffffu, v1m, 1));
            v1m = fmaxf(v1m, __shfl_xor_sync(0xffffffffu, v1m, 2));
            if ((pg & 3) == 0) {
                sm[SX1 + (o0  )*4 + nl] = v0m;
                sm[SX1 + (o0+1)*4 + nl] = v1m;
            }
        }
    }
    __syncthreads();
    loadTW<64,128,64,68>(sm + SWB, w2a, 0, tid);
    __syncthreads();

    // ---- P7: stage2 a main (K=64 on out1) ----
    u64 accA2[4][4];
#pragma unroll
    for (int op=0;op<4;op++)
#pragma unroll
        for (int p=0;p<4;p++) accA2[op][p]=0ull;
    gemm8<64>(sm + SWB, sm + SB, og, pg, accA2);
    __syncthreads();
    loadTW<64,128,64,68>(sm + SWB, w2a, 64, tid);
    __syncthreads();

    // ---- P9: stage2 a x1-corr ; h -> SA ----
    {
        u64 cr[4] = {0,0,0,0};
#pragma unroll 4
        for (int c = 0; c < 64; c++) {
            const float* wr = sm + SWB + c*68 + og*8;
            ulonglong2 w01 = *(const ulonglong2*)wr;
            ulonglong2 w23 = *(const ulonglong2*)(wr+4);
            float xv = sm[SX1 + c*4 + nl];
            u64 xs = pk2(xv, xv);
            fma2(cr[0], w01.x, xs); fma2(cr[1], w01.y, xs);
            fma2(cr[2], w23.x, xs); fma2(cr[3], w23.y, xs);
        }
#pragma unroll
        for (int op=0;op<4;op++) {
            int o0 = og*8 + 2*op;
            float2 c2 = up2(cr[op]);
            float b0 = __ldg(b2a + o0) + c2.x;
            float b1 = __ldg(b2a + o0 + 1) + c2.y;
#pragma unroll
            for (int p=0;p<4;p++) {
                float2 v = up2(accA2[op][p]);
                sm[SA + (o0  )*68 + pg*4 + p] = leaky(v.x + b0);
                sm[SA + (o0+1)*68 + pg*4 + p] = leaky(v.y + b1);
            }
        }
    }
    __syncthreads();

    // ---- stage2 b (K=64, two 32-chunks) ; h2 -> SA/SC ----
    u64 acc[8][4];
#pragma unroll
    for (int op=0;op<8;op++)
#pragma unroll
        for (int p=0;p<4;p++) acc[op][p]=0ull;
    loadTW<128,64,32,132>(sm + SWB, w2b, 0, tid);
    __syncthreads();
    gemm16<32>(sm + SWB, sm + SA, og, pg, acc);
    __syncthreads();
    loadTW<128,64,32,132>(sm + SWB, w2b, 32, tid);
    __syncthreads();
    gemm16<32>(sm + SWB, sm + SA + 32*68, og, pg, acc);
    __syncthreads();
    // write h2: ch<64 -> SA, ch>=64 -> SC
#pragma unroll
    for (int op=0;op<8;op++) {
        int o0 = og*16 + 2*op;
        float b0 = __ldg(b2b + o0), b1 = __ldg(b2b + o0+1);
        float* d0 = sm + ((o0 < 64) ? (SA + o0*68) : (SC + (o0-64)*68));
        float* d1 = sm + ((o0+1 < 64) ? (SA + (o0+1)*68) : (SC + (o0+1-64)*68));
#pragma unroll
        for (int p=0;p<4;p++) {
            float2 v = up2(acc[op][p]);
            d0[pg*4 + p] = leaky(v.x + b0);
            d1[pg*4 + p] = leaky(v.y + b1);
        }
    }
    loadTW<128,128,32,132>(sm + SWB, w2c, 0, tid);
    __syncthreads();

    // ---- stage2 c (K=128, four 32-chunks) + sc main (two) into one acc ----
#pragma unroll
    for (int op=0;op<8;op++)
#pragma unroll
        for (int p=0;p<4;p++) acc[op][p]=0ull;
    gemm16<32>(sm + SWB, sm + SA, og, pg, acc);
    __syncthreads();
    loadTW<128,128,32,132>(sm + SWB, w2c, 32, tid);
    __syncthreads();
    gemm16<32>(sm + SWB, sm + SA + 32*68, og, pg, acc);
    __syncthreads();
    loadTW<128,128,32,132>(sm + SWB, w2c, 64, tid);
    __syncthreads();
    gemm16<32>(sm + SWB, sm + SC, og, pg, acc);
    __syncthreads();
    loadTW<128,128,32,132>(sm + SWB, w2c, 96, tid);
    __syncthreads();
    gemm16<32>(sm + SWB, sm + SC + 32*68, og, pg, acc);
    __syncthreads();
    loadTW<128,128,32,132>(sm + SWB, w2sc, 0, tid);
    __syncthreads();
    gemm16<32>(sm + SWB, sm + SB, og, pg, acc);
    __syncthreads();
    loadTW<128,128,32,132>(sm + SWB, w2sc, 32, tid);
    __syncthreads();
    gemm16<32>(sm + SWB, sm + SB + 32*68, og, pg, acc);
    __syncthreads();

    // ---- sc x1-corr (two 32-col chunks) ----
    u64 cr2[8] = {0,0,0,0,0,0,0,0};
    loadTW<128,128,32,132>(sm + SWB, w2sc, 64, tid);
    __syncthreads();
#pragma unroll 4
    for (int c = 0; c < 32; c++) {
        const float* wr = sm + SWB + c*132 + og*16;
        ulonglong2 w01 = *(const ulonglong2*)wr;
        ulonglong2 w23 = *(const ulonglong2*)(wr+4);
        ulonglong2 w45 = *(const ulonglong2*)(wr+8);
        ulonglong2 w67 = *(const ulonglong2*)(wr+12);
        float xv = sm[SX1 + c*4 + nl];
        u64 xs = pk2(xv, xv);
        fma2(cr2[0], w01.x, xs); fma2(cr2[1], w01.y, xs);
        fma2(cr2[2], w23.x, xs); fma2(cr2[3], w23.y, xs);
        fma2(cr2[4], w45.x, xs); fma2(cr2[5], w45.y, xs);
        fma2(cr2[6], w67.x, xs); fma2(cr2[7], w67.y, xs);
    }
    __syncthreads();
    loadTW<128,128,32,132>(sm + SWB, w2sc, 96, tid);
    __syncthreads();
#pragma unroll 4
    for (int c = 0; c < 32; c++) {
        const float* wr = sm + SWB + c*132 + og*16;
        ulonglong2 w01 = *(const ulonglong2*)wr;
        ulonglong2 w23 = *(const ulonglong2*)(wr+4);
        ulonglong2 w45 = *(const ulonglong2*)(wr+8);
        ulonglong2 w67 = *(const ulonglong2*)(wr+12);
        float xv = sm[SX1 + (32+c)*4 + nl];
        u64 xs = pk2(xv, xv);
        fma2(cr2[0], w01.x, xs); fma2(cr2[1], w01.y, xs);
        fma2(cr2[2], w23.x, xs); fma2(cr2[3], w23.y, xs);
        fma2(cr2[4], w45.x, xs); fma2(cr2[5], w45.y, xs);
        fma2(cr2[6], w67.x, xs); fma2(cr2[7], w67.y, xs);
    }

    // ---- epilogue: +biases +corr, max over 16 k, write ----
#pragma unroll
    for (int op=0;op<8;op++) {
        int o0 = og*16 + 2*op;
        float2 c2 = up2(cr2[op]);
        float bt0 = __ldg(b2sc + o0)     + __ldg(b2c + o0)     + c2.x;
        float bt1 = __ldg(b2sc + o0 + 1) + __ldg(b2c + o0 + 1) + c2.y;
        float m0 = -3.4e38f, m1 = -3.4e38f;
#pragma unroll
        for (int p=0;p<4;p++) {
            float2 v = up2(acc[op][p]);
            m0 = fmaxf(m0, v.x); m1 = fmaxf(m1, v.y);
        }
        m0 += bt0; m1 += bt1;
        m0 = fmaxf(m0, __shfl_xor_sync(0xffffffffu, m0, 1));
        m0 = fmaxf(m0, __shfl_xor_sync(0xffffffffu, m0, 2));
        m1 = fmaxf(m1, __shfl_xor_sync(0xffffffffu, m1, 1));
        m1 = fmaxf(m1, __shfl_xor_sync(0xffffffffu, m1, 2));
        if ((pg & 3) == 0) {
            outp[((long long)b*128 + o0    )*NPTS + n0 + nl] = m0;
            outp[((long long)b*128 + o0 + 1)*NPTS + n0 + nl] = m1;
        }
    }
}

// =====================================================================
extern "C" void kernel_launch(void* const* d_in, const int* in_sizes, int n_in,
                              void* d_out, int out_size)
{
    const float* xyz     = (const float*)d_in[0];
    const float* p1_sc_w = (const float*)d_in[1];
    const float* p1_sc_b = (const float*)d_in[2];
    const float* p1_a_w  = (const float*)d_in[3];
    const float* p1_a_b  = (const float*)d_in[4];
    const float* p1_b_w  = (const float*)d_in[5];
    const float* p1_b_b  = (const float*)d_in[6];
    const float* p1_c_w  = (const float*)d_in[7];
    const float* p1_c_b  = (const float*)d_in[8];
    const float* p2_sc_w = (const float*)d_in[9];
    const float* p2_sc_b = (const float*)d_in[10];
    const float* p2_a_w  = (const float*)d_in[11];
    const float* p2_a_b  = (const float*)d_in[12];
    const float* p2_b_w  = (const float*)d_in[13];
    const float* p2_b_b  = (const float*)d_in[14];
    const float* p2_c_w  = (const float*)d_in[15];
    const float* p2_c_b  = (const float*)d_in[16];
    float* outp = (float*)d_out;

    cudaFuncSetAttribute(fused_kernel, cudaFuncAttributeMaxDynamicSharedMemorySize,
                         SMEM_FLOATS*4);

    knn_part<<<512, 128>>>(xyz);
    knn_merge<<<NQ/256, 256>>>();
    fused_kernel<<<NPOS/64, 128, SMEM_FLOATS*4>>>(
        xyz,
        p1_sc_w, p1_sc_b, p1_a_w, p1_a_b, p1_b_w, p1_b_b, p1_c_w, p1_c_b,
        p2_sc_w, p2_sc_b, p2_a_w, p2_a_b, p2_b_w, p2_b_b, p2_c_w, p2_c_b,
        outp);
}

// round 5
// speedup vs baseline: 1.9363x; 1.2773x over previous
#include <cuda_runtime.h>
#include <math.h>

#define BATCH 4
#define NPTS  8192
#define KNB   16
#define NPOS  (BATCH*NPTS*KNB)   // 524288
#define NQ    (BATCH*NPTS)       // 32768
#define CAP   48

__device__ int g_idx[NQ*KNB];
__device__ unsigned long long g_sbuf[(long long)NQ*2*CAP];   // (d, jbits) survivors
__device__ int g_scnt[NQ*2];

typedef unsigned long long u64;

__device__ __forceinline__ u64 pk2(float x, float y) {
    u64 r; asm("mov.b64 %0,{%1,%2};" : "=l"(r) : "f"(x), "f"(y)); return r;
}
__device__ __forceinline__ float2 up2(u64 v) {
    float2 r; asm("mov.b64 {%0,%1},%2;" : "=f"(r.x), "=f"(r.y) : "l"(v)); return r;
}
__device__ __forceinline__ void fma2(u64& d, u64 a, u64 b) {
    asm("fma.rn.f32x2 %0,%1,%2,%0;" : "+l"(d) : "l"(a), "l"(b));
}
__device__ __forceinline__ float leaky(float v) { return v >= 0.f ? v : 0.2f*v; }

// =====================================================================
// KNN part 1: branchless 2-pass top-16 over one 4096-candidate half.
// d' = ||xj||^2 - 2 xi.xj  (same ordering as true d2 for fixed i).
// =====================================================================
__global__ __launch_bounds__(128) void knn_part(const float* __restrict__ xyz)
{
    extern __shared__ float4 tile[];   // 4096 * 16B = 64KB (dynamic)
    const int tid  = threadIdx.x;
    const int half = blockIdx.x & 1;
    const int qb   = (blockIdx.x >> 1) & 63;
    const int b    = blockIdx.x >> 7;
    const int i    = qb*128 + tid;
    const float* xb = xyz + b*3*NPTS;
    const int c0 = half*4096;

    // load tile as (x,y,z,||p||^2)
    for (int l = tid; l < 1024; l += 128) {
        float4 vx = ((const float4*)(xb + c0))[l];
        float4 vy = ((const float4*)(xb + NPTS + c0))[l];
        float4 vz = ((const float4*)(xb + 2*NPTS + c0))[l];
        tile[4*l+0] = make_float4(vx.x, vy.x, vz.x, fmaf(vx.x,vx.x, fmaf(vy.x,vy.x, vz.x*vz.x)));
        tile[4*l+1] = make_float4(vx.y, vy.y, vz.y, fmaf(vx.y,vx.y, fmaf(vy.y,vy.y, vz.y*vz.y)));
        tile[4*l+2] = make_float4(vx.z, vy.z, vz.z, fmaf(vx.z,vx.z, fmaf(vy.z,vy.z, vz.z*vz.z)));
        tile[4*l+3] = make_float4(vx.w, vy.w, vz.w, fmaf(vx.w,vx.w, fmaf(vy.w,vy.w, vz.w*vz.w)));
    }
    __syncthreads();

    const float x2 = -2.0f*xb[i], y2 = -2.0f*xb[NPTS+i], z2 = -2.0f*xb[2*NPTS+i];

    // ---- pass A: 32 residue-slot minima, fully branchless ----
    float s[32];
#pragma unroll
    for (int t = 0; t < 32; t++) s[t] = 3.4e38f;
    for (int j0 = 0; j0 < 4096; j0 += 32) {
#pragma unroll
        for (int u = 0; u < 32; u++) {
            float4 p = tile[j0+u];
            float d = fmaf(x2, p.x, fmaf(y2, p.y, fmaf(z2, p.z, p.w)));
            s[u] = fminf(s[u], d);
        }
    }

    // ---- bitonic sort the 32 slots (ascending), T = 16th smallest ----
#pragma unroll
    for (int k = 2; k <= 32; k <<= 1) {
#pragma unroll
        for (int j = k >> 1; j > 0; j >>= 1) {
#pragma unroll
            for (int ii = 0; ii < 32; ii++) {
                int l = ii ^ j;
                if (l > ii) {
                    float lo = fminf(s[ii], s[l]);
                    float hi = fmaxf(s[ii], s[l]);
                    bool up = ((ii & k) == 0);
                    s[ii] = up ? lo : hi;
                    s[l]  = up ? hi : lo;
                }
            }
        }
    }
    const float T = s[15];

    // ---- pass B: collect survivors (d <= T); guaranteed >= 16 ----
    u64 buf[CAP];
    int cnt = 0, ovf = 0;
    for (int j = 0; j < 4096; j++) {
        float4 p = tile[j];
        float d = fmaf(x2, p.x, fmaf(y2, p.y, fmaf(z2, p.z, p.w)));
        if (d <= T) {
            if (cnt < CAP) { buf[cnt] = pk2(d, __int_as_float(c0+j)); cnt++; }
            else ovf = 1;
        }
    }

    if (ovf) {   // astronomically rare: exact top-16 fallback for this lane
        float bd[16]; int bj[16];
#pragma unroll
        for (int t = 0; t < 16; t++) { bd[t] = 3.4e38f; bj[t] = 0; }
        float cm = 3.4e38f;
        for (int j = 0; j < 4096; j++) {
            float4 p = tile[j];
            float d = fmaf(x2, p.x, fmaf(y2, p.y, fmaf(z2, p.z, p.w)));
            if (d < cm) {
                int am = 0; float mv = bd[0];
#pragma unroll
                for (int u = 1; u < 16; u++) if (bd[u] > mv) { mv = bd[u]; am = u; }
#pragma unroll
                for (int u = 0; u < 16; u++) if (u == am) { bd[u] = d; bj[u] = c0 + j; }
                cm = bd[0];
#pragma unroll
                for (int u = 1; u < 16; u++) cm = fmaxf(cm, bd[u]);
            }
        }
        cnt = 16;
#pragma unroll
        for (int t = 0; t < 16; t++) buf[t] = pk2(bd[t], __int_as_float(bj[t]));
    }

    const int qg = b*NPTS + i;
    g_scnt[qg*2 + half] = cnt;
    u64* dst = g_sbuf + (long long)(qg*2 + half)*CAP;
    for (int t = 0; t < cnt; t++) dst[t] = buf[t];
}

// =====================================================================
// KNN part 2: exact top-16 over pooled survivors of both halves
// =====================================================================
__global__ __launch_bounds__(256) void knn_merge()
{
    const int q = blockIdx.x*256 + threadIdx.x;
    float bd[16]; int bj[16];
#pragma unroll
    for (int t = 0; t < 16; t++) { bd[t] = 3.4e38f; bj[t] = 0; }
    float cm = 3.4e38f;
#pragma unroll
    for (int h = 0; h < 2; h++) {
        const int c = g_scnt[q*2 + h];
        const u64* src = g_sbuf + (long long)(q*2 + h)*CAP;
        for (int e = 0; e < c; e++) {
            float2 v = up2(src[e]);
            float d = v.x;
            if (d < cm) {
                int am = 0; float mv = bd[0];
#pragma unroll
                for (int u = 1; u < 16; u++) if (bd[u] > mv) { mv = bd[u]; am = u; }
#pragma unroll
                for (int u = 0; u < 16; u++) if (u == am) { bd[u] = d; bj[u] = __float_as_int(v.y); }
                cm = bd[0];
#pragma unroll
                for (int u = 1; u < 16; u++) cm = fmaxf(cm, bd[u]);
            }
        }
    }
#pragma unroll
    for (int t = 0; t < 16; t++) g_idx[q*16 + t] = bj[t];
}

// =====================================================================
// smem layout (floats) — fused kernel (unchanged from R4)
// =====================================================================
#define SA    0
#define SB    4352
#define SC    8704
#define SWB   13056
#define SX1   17408
#define SBIAS 17664
#define SMEM_FLOATS 17920   // 71680 B -> 3 CTAs/SM

template<int OR, int KFULL, int KLEN, int WS>
__device__ __forceinline__ void loadTW(float* __restrict__ dst,
                                       const float* __restrict__ src,
                                       int koff, int tid)
{
    constexpr int ITERS = OR*(KLEN/4)/128;
#pragma unroll
    for (int it = 0; it < ITERS; it++) {
        int l = it*128 + tid;
        int o  = l & (OR-1);
        int k4 = l >> (OR == 128 ? 7 : 6);
        float4 v = *(const float4*)(src + o*KFULL + koff + 4*k4);
        int k = 4*k4;
        dst[(k  )*WS + o] = v.x;
        dst[(k+1)*WS + o] = v.y;
        dst[(k+2)*WS + o] = v.z;
        dst[(k+3)*WS + o] = v.w;
    }
}

template<int KS>
__device__ __forceinline__ void gemm16(const float* __restrict__ w,
                                       const float* __restrict__ a,
                                       int og, int pg, u64 acc[8][4])
{
#pragma unroll 4
    for (int k = 0; k < KS; k++) {
        const float* wr = w + k*132 + og*16;
        ulonglong2 w01 = *(const ulonglong2*)wr;
        ulonglong2 w23 = *(const ulonglong2*)(wr+4);
        ulonglong2 w45 = *(const ulonglong2*)(wr+8);
        ulonglong2 w67 = *(const ulonglong2*)(wr+12);
        u64 wp[8] = {w01.x,w01.y,w23.x,w23.y,w45.x,w45.y,w67.x,w67.y};
        float4 av = *(const float4*)(a + k*68 + pg*4);
        u64 as[4] = {pk2(av.x,av.x), pk2(av.y,av.y), pk2(av.z,av.z), pk2(av.w,av.w)};
#pragma unroll
        for (int op = 0; op < 8; op++)
#pragma unroll
            for (int p = 0; p < 4; p++) fma2(acc[op][p], wp[op], as[p]);
    }
}

template<int KS>
__device__ __forceinline__ void gemm8(const float* __restrict__ w,
                                      const float* __restrict__ a,
                                      int og, int pg, u64 acc[4][4])
{
#pragma unroll 4
    for (int k = 0; k < KS; k++) {
        const float* wr = w + k*68 + og*8;
        ulonglong2 w01 = *(const ulonglong2*)wr;
        ulonglong2 w23 = *(const ulonglong2*)(wr+4);
        u64 wp[4] = {w01.x,w01.y,w23.x,w23.y};
        float4 av = *(const float4*)(a + k*68 + pg*4);
        u64 as[4] = {pk2(av.x,av.x), pk2(av.y,av.y), pk2(av.z,av.z), pk2(av.w,av.w)};
#pragma unroll
        for (int op = 0; op < 4; op++)
#pragma unroll
            for (int p = 0; p < 4; p++) fma2(acc[op][p], wp[op], as[p]);
    }
}

__global__ void __launch_bounds__(128,3) fused_kernel(
    const float* __restrict__ xyz,
    const float* __restrict__ w1sc, const float* __restrict__ b1sc,
    const float* __restrict__ w1a,  const float* __restrict__ b1a,
    const float* __restrict__ w1b,  const float* __restrict__ b1b,
    const float* __restrict__ w1c,  const float* __restrict__ b1c,
    const float* __restrict__ w2sc, const float* __restrict__ b2sc,
    const float* __restrict__ w2a,  const float* __restrict__ b2a,
    const float* __restrict__ w2b,  const float* __restrict__ b2b,
    const float* __restrict__ w2c,  const float* __restrict__ b2c,
    float* __restrict__ outp)
{
    extern __shared__ float sm[];
    const int tid = threadIdx.x;
    const int pg = tid & 15, og = tid >> 4;
    const int base = blockIdx.x << 6;
    const int b  = base >> 17;
    const int n0 = (base & (NPTS*KNB - 1)) >> 4;
    const int nl = pg >> 2;

    loadTW<64,64,64,68>(sm + SWB, w1b, 0, tid);
    for (int l = tid; l < 640; l += 128) {
        int o = l/10, k = l - o*10;
        sm[SC + 680  + k*68 + o] = w1sc[l];
        sm[SC + 1360 + k*68 + o] = w1a[l];
    }
    if (tid < 64) {
        sm[SBIAS+tid] = b1sc[tid]; sm[SBIAS+64+tid] = b1a[tid];
        sm[SBIAS+128+tid] = b1b[tid]; sm[SBIAS+192+tid] = b1c[tid];
    }
    if (tid < 64) {
        int nn = n0 + (tid >> 4);
        const float* xb = xyz + b*3*NPTS;
        int j = g_idx[(b*NPTS + nn)*KNB + (tid & 15)];
        float cx = xb[nn], cy = xb[NPTS+nn], cz = xb[2*NPTS+nn];
        float nx = xb[j],  ny = xb[NPTS+j],  nz = xb[2*NPTS+j];
        float rx = nx-cx, ry = ny-cy, rz = nz-cz;
        float dd = sqrtf(fmaf(rx,rx, fmaf(ry,ry, rz*rz)) + 1e-12f);
        sm[SC+0*68+tid]=cx; sm[SC+1*68+tid]=cy; sm[SC+2*68+tid]=cz;
        sm[SC+3*68+tid]=nx; sm[SC+4*68+tid]=ny; sm[SC+5*68+tid]=nz;
        sm[SC+6*68+tid]=rx; sm[SC+7*68+tid]=ry; sm[SC+8*68+tid]=rz;
        sm[SC+9*68+tid]=dd;
    }
    __syncthreads();

    // stage1 sc + a (K=10)
    {
        u64 accS[4][4], accA[4][4];
#pragma unroll
        for (int op=0;op<4;op++)
#pragma unroll
            for (int p=0;p<4;p++) { accS[op][p]=0ull; accA[op][p]=0ull; }
#pragma unroll
        for (int k = 0; k < 10; k++) {
            const float* wsr = sm + SC + 680  + k*68 + og*8;
            const float* war = sm + SC + 1360 + k*68 + og*8;
            ulonglong2 ws01 = *(const ulonglong2*)wsr;
            ulonglong2 ws23 = *(const ulonglong2*)(wsr+4);
            ulonglong2 wa01 = *(const ulonglong2*)war;
            ulonglong2 wa23 = *(const ulonglong2*)(war+4);
            u64 wsp[4] = {ws01.x,ws01.y,ws23.x,ws23.y};
            u64 wap[4] = {wa01.x,wa01.y,wa23.x,wa23.y};
            float4 av = *(const float4*)(sm + SC + k*68 + pg*4);
            u64 as[4] = {pk2(av.x,av.x), pk2(av.y,av.y), pk2(av.z,av.z), pk2(av.w,av.w)};
#pragma unroll
            for (int op=0;op<4;op++)
#pragma unroll
                for (int p=0;p<4;p++) { fma2(accS[op][p], wsp[op], as[p]); fma2(accA[op][p], wap[op], as[p]); }
        }
#pragma unroll
        for (int op=0;op<4;op++) {
            int o0 = og*8 + 2*op;
            float ba0 = sm[SBIAS+64+o0], ba1 = sm[SBIAS+64+o0+1];
#pragma unroll
            for (int p=0;p<4;p++) {
                float2 va = up2(accA[op][p]);
                sm[SA + (o0  )*68 + pg*4 + p] = leaky(va.x + ba0);
                sm[SA + (o0+1)*68 + pg*4 + p] = leaky(va.y + ba1);
                float2 vs = up2(accS[op][p]);
                sm[SB + (o0  )*68 + pg*4 + p] = vs.x;
                sm[SB + (o0+1)*68 + pg*4 + p] = vs.y;
            }
        }
    }
    __syncthreads();

    // stage1 b
    {
        u64 acc[4][4];
#pragma unroll
        for (int op=0;op<4;op++)
#pragma unroll
            for (int p=0;p<4;p++) acc[op][p]=0ull;
        gemm8<64>(sm + SWB, sm + SA, og, pg, acc);
#pragma unroll
        for (int op=0;op<4;op++) {
            int o0 = og*8 + 2*op;
            float b0 = sm[SBIAS+128+o0], b1 = sm[SBIAS+128+o0+1];
#pragma unroll
            for (int p=0;p<4;p++) {
                float2 v = up2(acc[op][p]);
                sm[SC + (o0  )*68 + pg*4 + p] = leaky(v.x + b0);
                sm[SC + (o0+1)*68 + pg*4 + p] = leaky(v.y + b1);
            }
        }
    }
    __syncthreads();
    loadTW<64,64,64,68>(sm + SWB, w1c, 0, tid);
    __syncthreads();

    // stage1 c + out1 + x1
    {
        u64 acc[4][4];
#pragma unroll
        for (int op=0;op<4;op++)
#pragma unroll
            for (int p=0;p<4;p++) acc[op][p]=0ull;
        gemm8<64>(sm + SWB, sm + SC, og, pg, acc);
#pragma unroll
        for (int op=0;op<4;op++) {
            int o0 = og*8 + 2*op;
            float bt0 = sm[SBIAS+192+o0] + sm[SBIAS+o0];
            float bt1 = sm[SBIAS+192+o0+1] + sm[SBIAS+o0+1];
            float v0m = -3.4e38f, v1m = -3.4e38f;
#pragma unroll
            for (int p=0;p<4;p++) {
                float2 v = up2(acc[op][p]);
                float o0v = v.x + sm[SB + (o0  )*68 + pg*4 + p] + bt0;
                float o1v = v.y + sm[SB + (o0+1)*68 + pg*4 + p] + bt1;
                sm[SB + (o0  )*68 + pg*4 + p] = o0v;
                sm[SB + (o0+1)*68 + pg*4 + p] = o1v;
                v0m = fmaxf(v0m, o0v); v1m = fmaxf(v1m, o1v);
            }
            v0m = fmaxf(v0m, __shfl_xor_sync(0xffffffffu, v0m, 1));
            v0m = fmaxf(v0m, __shfl_xor_sync(0xffffffffu, v0m, 2));
            v1m = fmaxf(v1m, __shfl_xor_sync(0xffffffffu, v1m, 1));
            v1m = fmaxf(v1m, __shfl_xor_sync(0xffffffffu, v1m, 2));
            if ((pg & 3) == 0) {
                sm[SX1 + (o0  )*4 + nl] = v0m;
                sm[SX1 + (o0+1)*4 + nl] = v1m;
            }
        }
    }
    __syncthreads();
    loadTW<64,128,64,68>(sm + SWB, w2a, 0, tid);
    __syncthreads();

    // stage2 a main
    u64 accA2[4][4];
#pragma unroll
    for (int op=0;op<4;op++)
#pragma unroll
        for (int p=0;p<4;p++) accA2[op][p]=0ull;
    gemm8<64>(sm + SWB, sm + SB, og, pg, accA2);
    __syncthreads();
    loadTW<64,128,64,68>(sm + SWB, w2a, 64, tid);
    __syncthreads();

    // stage2 a x1-corr
    {
        u64 cr[4] = {0,0,0,0};
#pragma unroll 4
        for (int c = 0; c < 64; c++) {
            const float* wr = sm + SWB + c*68 + og*8;
            ulonglong2 w01 = *(const ulonglong2*)wr;
            ulonglong2 w23 = *(const ulonglong2*)(wr+4);
            float xv = sm[SX1 + c*4 + nl];
            u64 xs = pk2(xv, xv);
            fma2(cr[0], w01.x, xs); fma2(cr[1], w01.y, xs);
            fma2(cr[2], w23.x, xs); fma2(cr[3], w23.y, xs);
        }
#pragma unroll
        for (int op=0;op<4;op++) {
            int o0 = og*8 + 2*op;
            float2 c2 = up2(cr[op]);
            float b0 = __ldg(b2a + o0) + c2.x;
            float b1 = __ldg(b2a + o0 + 1) + c2.y;
#pragma unroll
            for (int p=0;p<4;p++) {
                float2 v = up2(accA2[op][p]);
                sm[SA + (o0  )*68 + pg*4 + p] = leaky(v.x + b0);
                sm[SA + (o0+1)*68 + pg*4 + p] = leaky(v.y + b1);
            }
        }
    }
    __syncthreads();

    // stage2 b
    u64 acc[8][4];
#pragma unroll
    for (int op=0;op<8;op++)
#pragma unroll
        for (int p=0;p<4;p++) acc[op][p]=0ull;
    loadTW<128,64,32,132>(sm + SWB, w2b, 0, tid);
    __syncthreads();
    gemm16<32>(sm + SWB, sm + SA, og, pg, acc);
    __syncthreads();
    loadTW<128,64,32,132>(sm + SWB, w2b, 32, tid);
    __syncthreads();
    gemm16<32>(sm + SWB, sm + SA + 32*68, og, pg, acc);
    __syncthreads();
#pragma unroll
    for (int op=0;op<8;op++) {
        int o0 = og*16 + 2*op;
        float b0 = __ldg(b2b + o0), b1 = __ldg(b2b + o0+1);
        float* d0 = sm + ((o0 < 64) ? (SA + o0*68) : (SC + (o0-64)*68));
        float* d1 = sm + ((o0+1 < 64) ? (SA + (o0+1)*68) : (SC + (o0+1-64)*68));
#pragma unroll
        for (int p=0;p<4;p++) {
            float2 v = up2(acc[op][p]);
            d0[pg*4 + p] = leaky(v.x + b0);
            d1[pg*4 + p] = leaky(v.y + b1);
        }
    }
    loadTW<128,128,32,132>(sm + SWB, w2c, 0, tid);
    __syncthreads();

    // stage2 c + sc main
#pragma unroll
    for (int op=0;op<8;op++)
#pragma unroll
        for (int p=0;p<4;p++) acc[op][p]=0ull;
    gemm16<32>(sm + SWB, sm + SA, og, pg, acc);
    __syncthreads();
    loadTW<128,128,32,132>(sm + SWB, w2c, 32, tid);
    __syncthreads();
    gemm16<32>(sm + SWB, sm + SA + 32*68, og, pg, acc);
    __syncthreads();
    loadTW<128,128,32,132>(sm + SWB, w2c, 64, tid);
    __syncthreads();
    gemm16<32>(sm + SWB, sm + SC, og, pg, acc);
    __syncthreads();
    loadTW<128,128,32,132>(sm + SWB, w2c, 96, tid);
    __syncthreads();
    gemm16<32>(sm + SWB, sm + SC + 32*68, og, pg, acc);
    __syncthreads();
    loadTW<128,128,32,132>(sm + SWB, w2sc, 0, tid);
    __syncthreads();
    gemm16<32>(sm + SWB, sm + SB, og, pg, acc);
    __syncthreads();
    loadTW<128,128,32,132>(sm + SWB, w2sc, 32, tid);
    __syncthreads();
    gemm16<32>(sm + SWB, sm + SB + 32*68, og, pg, acc);
    __syncthreads();

    // sc x1-corr
    u64 cr2[8] = {0,0,0,0,0,0,0,0};
    loadTW<128,128,32,132>(sm + SWB, w2sc, 64, tid);
    __syncthreads();
#pragma unroll 4
    for (int c = 0; c < 32; c++) {
        const float* wr = sm + SWB + c*132 + og*16;
        ulonglong2 w01 = *(const ulonglong2*)wr;
        ulonglong2 w23 = *(const ulonglong2*)(wr+4);
        ulonglong2 w45 = *(const ulonglong2*)(wr+8);
        ulonglong2 w67 = *(const ulonglong2*)(wr+12);
        float xv = sm[SX1 + c*4 + nl];
        u64 xs = pk2(xv, xv);
        fma2(cr2[0], w01.x, xs); fma2(cr2[1], w01.y, xs);
        fma2(cr2[2], w23.x, xs); fma2(cr2[3], w23.y, xs);
        fma2(cr2[4], w45.x, xs); fma2(cr2[5], w45.y, xs);
        fma2(cr2[6], w67.x, xs); fma2(cr2[7], w67.y, xs);
    }
    __syncthreads();
    loadTW<128,128,32,132>(sm + SWB, w2sc, 96, tid);
    __syncthreads();
#pragma unroll 4
    for (int c = 0; c < 32; c++) {
        const float* wr = sm + SWB + c*132 + og*16;
        ulonglong2 w01 = *(const ulonglong2*)wr;
        ulonglong2 w23 = *(const ulonglong2*)(wr+4);
        ulonglong2 w45 = *(const ulonglong2*)(wr+8);
        ulonglong2 w67 = *(const ulonglong2*)(wr+12);
        float xv = sm[SX1 + (32+c)*4 + nl];
        u64 xs = pk2(xv, xv);
        fma2(cr2[0], w01.x, xs); fma2(cr2[1], w01.y, xs);
        fma2(cr2[2], w23.x, xs); fma2(cr2[3], w23.y, xs);
        fma2(cr2[4], w45.x, xs); fma2(cr2[5], w45.y, xs);
        fma2(cr2[6], w67.x, xs); fma2(cr2[7], w67.y, xs);
    }

#pragma unroll
    for (int op=0;op<8;op++) {
        int o0 = og*16 + 2*op;
        float2 c2 = up2(cr2[op]);
        float bt0 = __ldg(b2sc + o0)     + __ldg(b2c + o0)     + c2.x;
        float bt1 = __ldg(b2sc + o0 + 1) + __ldg(b2c + o0 + 1) + c2.y;
        float m0 = -3.4e38f, m1 = -3.4e38f;
#pragma unroll
        for (int p=0;p<4;p++) {
            float2 v = up2(acc[op][p]);
            m0 = fmaxf(m0, v.x); m1 = fmaxf(m1, v.y);
        }
        m0 += bt0; m1 += bt1;
        m0 = fmaxf(m0, __shfl_xor_sync(0xffffffffu, m0, 1));
        m0 = fmaxf(m0, __shfl_xor_sync(0xffffffffu, m0, 2));
        m1 = fmaxf(m1, __shfl_xor_sync(0xffffffffu, m1, 1));
        m1 = fmaxf(m1, __shfl_xor_sync(0xffffffffu, m1, 2));
        if ((pg & 3) == 0) {
            outp[((long long)b*128 + o0    )*NPTS + n0 + nl] = m0;
            outp[((long long)b*128 + o0 + 1)*NPTS + n0 + nl] = m1;
        }
    }
}

// =====================================================================
extern "C" void kernel_launch(void* const* d_in, const int* in_sizes, int n_in,
                              void* d_out, int out_size)
{
    const float* xyz     = (const float*)d_in[0];
    const float* p1_sc_w = (const float*)d_in[1];
    const float* p1_sc_b = (const float*)d_in[2];
    const float* p1_a_w  = (const float*)d_in[3];
    const float* p1_a_b  = (const float*)d_in[4];
    const float* p1_b_w  = (const float*)d_in[5];
    const float* p1_b_b  = (const float*)d_in[6];
    const float* p1_c_w  = (const float*)d_in[7];
    const float* p1_c_b  = (const float*)d_in[8];
    const float* p2_sc_w = (const float*)d_in[9];
    const float* p2_sc_b = (const float*)d_in[10];
    const float* p2_a_w  = (const float*)d_in[11];
    const float* p2_a_b  = (const float*)d_in[12];
    const float* p2_b_w  = (const float*)d_in[13];
    const float* p2_b_b  = (const float*)d_in[14];
    const float* p2_c_w  = (const float*)d_in[15];
    const float* p2_c_b  = (const float*)d_in[16];
    float* outp = (float*)d_out;

    cudaFuncSetAttribute(knn_part, cudaFuncAttributeMaxDynamicSharedMemorySize, 65536);
    cudaFuncSetAttribute(fused_kernel, cudaFuncAttributeMaxDynamicSharedMemorySize,
                         SMEM_FLOATS*4);

    knn_part<<<512, 128, 65536>>>(xyz);
    knn_merge<<<NQ/256, 256>>>();
    fused_kernel<<<NPOS/64, 128, SMEM_FLOATS*4>>>(
        xyz,
        p1_sc_w, p1_sc_b, p1_a_w, p1_a_b, p1_b_w, p1_b_b, p1_c_w, p1_c_b,
        p2_sc_w, p2_sc_b, p2_a_w, p2_a_b, p2_b_w, p2_b_b, p2_c_w, p2_c_b,
        outp);
}

// round 6
// speedup vs baseline: 2.0118x; 1.0390x over previous
#include <cuda_runtime.h>
#include <math.h>

#define BATCH 4
#define NPTS  8192
#define KNB   16
#define NPOS  (BATCH*NPTS*KNB)   // 524288
#define NQ    (BATCH*NPTS)       // 32768
#define CAP   48
#define NPART 4

__device__ int g_idx[NQ*KNB];
__device__ unsigned long long g_sbuf[(long long)NQ*NPART*CAP];
__device__ int g_scnt[NQ*NPART];

typedef unsigned long long u64;

__device__ __forceinline__ u64 pk2(float x, float y) {
    u64 r; asm("mov.b64 %0,{%1,%2};" : "=l"(r) : "f"(x), "f"(y)); return r;
}
__device__ __forceinline__ float2 up2(u64 v) {
    float2 r; asm("mov.b64 {%0,%1},%2;" : "=f"(r.x), "=f"(r.y) : "l"(v)); return r;
}
__device__ __forceinline__ void fma2(u64& d, u64 a, u64 b) {
    asm("fma.rn.f32x2 %0,%1,%2,%0;" : "+l"(d) : "l"(a), "l"(b));
}
__device__ __forceinline__ float leaky(float v) { return v >= 0.f ? v : 0.2f*v; }

// =====================================================================
// KNN part 1: branchless 2-pass top-16 over one 2048-candidate quarter.
// 1024 blocks x 128 thr, 32KB smem -> 7 CTAs/SM, single wave.
// =====================================================================
__global__ __launch_bounds__(128) void knn_part(const float* __restrict__ xyz)
{
    extern __shared__ float4 tile[];   // 2048 * 16B = 32KB
    const int tid = threadIdx.x;
    const int quarter = blockIdx.x & 3;
    const int qb = (blockIdx.x >> 2) & 63;
    const int b  = blockIdx.x >> 8;
    const int i  = qb*128 + tid;
    const float* xb = xyz + b*3*NPTS;
    const int c0 = quarter*2048;

    for (int l = tid; l < 512; l += 128) {
        float4 vx = ((const float4*)(xb + c0))[l];
        float4 vy = ((const float4*)(xb + NPTS + c0))[l];
        float4 vz = ((const float4*)(xb + 2*NPTS + c0))[l];
        tile[4*l+0] = make_float4(vx.x, vy.x, vz.x, fmaf(vx.x,vx.x, fmaf(vy.x,vy.x, vz.x*vz.x)));
        tile[4*l+1] = make_float4(vx.y, vy.y, vz.y, fmaf(vx.y,vx.y, fmaf(vy.y,vy.y, vz.y*vz.y)));
        tile[4*l+2] = make_float4(vx.z, vy.z, vz.z, fmaf(vx.z,vx.z, fmaf(vy.z,vy.z, vz.z*vz.z)));
        tile[4*l+3] = make_float4(vx.w, vy.w, vz.w, fmaf(vx.w,vx.w, fmaf(vy.w,vy.w, vz.w*vz.w)));
    }
    __syncthreads();

    const float x2 = -2.0f*xb[i], y2 = -2.0f*xb[NPTS+i], z2 = -2.0f*xb[2*NPTS+i];

    // pass A: 32 residue-slot minima, branchless
    float s[32];
#pragma unroll
    for (int t = 0; t < 32; t++) s[t] = 3.4e38f;
    for (int j0 = 0; j0 < 2048; j0 += 32) {
#pragma unroll
        for (int u = 0; u < 32; u++) {
            float4 p = tile[j0+u];
            float d = fmaf(x2, p.x, fmaf(y2, p.y, fmaf(z2, p.z, p.w)));
            s[u] = fminf(s[u], d);
        }
    }

    // bitonic sort 32 slots; T = 16th smallest
#pragma unroll
    for (int k = 2; k <= 32; k <<= 1) {
#pragma unroll
        for (int j = k >> 1; j > 0; j >>= 1) {
#pragma unroll
            for (int ii = 0; ii < 32; ii++) {
                int l = ii ^ j;
                if (l > ii) {
                    float lo = fminf(s[ii], s[l]);
                    float hi = fmaxf(s[ii], s[l]);
                    bool up = ((ii & k) == 0);
                    s[ii] = up ? lo : hi;
                    s[l]  = up ? hi : lo;
                }
            }
        }
    }
    const float T = s[15];

    // pass B: collect survivors (>=16 guaranteed)
    u64 buf[CAP];
    int cnt = 0, ovf = 0;
    for (int j = 0; j < 2048; j++) {
        float4 p = tile[j];
        float d = fmaf(x2, p.x, fmaf(y2, p.y, fmaf(z2, p.z, p.w)));
        if (d <= T) {
            if (cnt < CAP) { buf[cnt] = pk2(d, __int_as_float(c0+j)); cnt++; }
            else ovf = 1;
        }
    }

    if (ovf) {   // astronomically rare exact fallback
        float bd[16]; int bj[16];
#pragma unroll
        for (int t = 0; t < 16; t++) { bd[t] = 3.4e38f; bj[t] = 0; }
        float cm = 3.4e38f;
        for (int j = 0; j < 2048; j++) {
            float4 p = tile[j];
            float d = fmaf(x2, p.x, fmaf(y2, p.y, fmaf(z2, p.z, p.w)));
            if (d < cm) {
                int am = 0; float mv = bd[0];
#pragma unroll
                for (int u = 1; u < 16; u++) if (bd[u] > mv) { mv = bd[u]; am = u; }
#pragma unroll
                for (int u = 0; u < 16; u++) if (u == am) { bd[u] = d; bj[u] = c0 + j; }
                cm = bd[0];
#pragma unroll
                for (int u = 1; u < 16; u++) cm = fmaxf(cm, bd[u]);
            }
        }
        cnt = 16;
#pragma unroll
        for (int t = 0; t < 16; t++) buf[t] = pk2(bd[t], __int_as_float(bj[t]));
    }

    const int qg = b*NPTS + i;
    g_scnt[qg*NPART + quarter] = cnt;
    u64* dst = g_sbuf + (long long)(qg*NPART + quarter)*CAP;
    for (int t = 0; t < cnt; t++) dst[t] = buf[t];
}

// =====================================================================
// KNN part 2: exact top-16 over pooled survivors (4 parts)
// =====================================================================
__global__ __launch_bounds__(256) void knn_merge()
{
    const int q = blockIdx.x*256 + threadIdx.x;
    float bd[16]; int bj[16];
#pragma unroll
    for (int t = 0; t < 16; t++) { bd[t] = 3.4e38f; bj[t] = 0; }
    float cm = 3.4e38f;
#pragma unroll
    for (int h = 0; h < NPART; h++) {
        const int c = g_scnt[q*NPART + h];
        const u64* src = g_sbuf + (long long)(q*NPART + h)*CAP;
        for (int e = 0; e < c; e++) {
            float2 v = up2(src[e]);
            float d = v.x;
            if (d < cm) {
                int am = 0; float mv = bd[0];
#pragma unroll
                for (int u = 1; u < 16; u++) if (bd[u] > mv) { mv = bd[u]; am = u; }
#pragma unroll
                for (int u = 0; u < 16; u++) if (u == am) { bd[u] = d; bj[u] = __float_as_int(v.y); }
                cm = bd[0];
#pragma unroll
                for (int u = 1; u < 16; u++) cm = fmaxf(cm, bd[u]);
            }
        }
    }
#pragma unroll
    for (int t = 0; t < 16; t++) g_idx[q*16 + t] = bj[t];
}

// =====================================================================
// smem layout (floats)
// =====================================================================
#define SA    0        // 4352
#define SB    4352     // 4352
#define SC    8704     // 4352
#define SW0   13056    // 2176 ping
#define SW1   15232    // 2176 pong
#define SX1   17408    // 256
#define SBIAS 17664    // 256
#define SMEM_FLOATS 17920   // 71680 B -> 3 CTAs/SM

// ---- pipelined weight load helpers: LDG->regs, STS->smem k-major ----
// type A: 64-out, 32-k chunk (dst stride 68, 2048 floats)
template<int KFULL>
__device__ __forceinline__ void ldgA(float4 r[4], const float* __restrict__ src,
                                     int koff, int tid)
{
#pragma unroll
    for (int it = 0; it < 4; it++) {
        int l = it*128 + tid;
        int o = l & 63, k4 = l >> 6;
        r[it] = *(const float4*)(src + o*KFULL + koff + 4*k4);
    }
}
__device__ __forceinline__ void stsA(float* __restrict__ dst, const float4 r[4], int tid)
{
#pragma unroll
    for (int it = 0; it < 4; it++) {
        int l = it*128 + tid;
        int o = l & 63, k = (l >> 6)*4;
        dst[(k  )*68+o] = r[it].x; dst[(k+1)*68+o] = r[it].y;
        dst[(k+2)*68+o] = r[it].z; dst[(k+3)*68+o] = r[it].w;
    }
}
// type B: 128-out, 16-k chunk (dst stride 132, 2048 floats)
template<int KFULL>
__device__ __forceinline__ void ldgB(float4 r[4], const float* __restrict__ src,
                                     int koff, int tid)
{
#pragma unroll
    for (int it = 0; it < 4; it++) {
        int l = it*128 + tid;
        int o = l & 127, k4 = l >> 7;
        r[it] = *(const float4*)(src + o*KFULL + koff + 4*k4);
    }
}
__device__ __forceinline__ void stsB(float* __restrict__ dst, const float4 r[4], int tid)
{
#pragma unroll
    for (int it = 0; it < 4; it++) {
        int l = it*128 + tid;
        int o = l & 127, k = (l >> 7)*4;
        dst[(k  )*132+o] = r[it].x; dst[(k+1)*132+o] = r[it].y;
        dst[(k+2)*132+o] = r[it].z; dst[(k+3)*132+o] = r[it].w;
    }
}

// 16 out (8 pairs) x 4 pos. w: [k][o] stride 132.
template<int KS>
__device__ __forceinline__ void gemm16(const float* __restrict__ w,
                                       const float* __restrict__ a,
                                       int og, int pg, u64 acc[8][4])
{
#pragma unroll 4
    for (int k = 0; k < KS; k++) {
        const float* wr = w + k*132 + og*16;
        ulonglong2 w01 = *(const ulonglong2*)wr;
        ulonglong2 w23 = *(const ulonglong2*)(wr+4);
        ulonglong2 w45 = *(const ulonglong2*)(wr+8);
        ulonglong2 w67 = *(const ulonglong2*)(wr+12);
        u64 wp[8] = {w01.x,w01.y,w23.x,w23.y,w45.x,w45.y,w67.x,w67.y};
        float4 av = *(const float4*)(a + k*68 + pg*4);
        u64 as[4] = {pk2(av.x,av.x), pk2(av.y,av.y), pk2(av.z,av.z), pk2(av.w,av.w)};
#pragma unroll
        for (int op = 0; op < 8; op++)
#pragma unroll
            for (int p = 0; p < 4; p++) fma2(acc[op][p], wp[op], as[p]);
    }
}

// 8 out (4 pairs) x 4 pos. w: [k][o] stride 68.
template<int KS>
__device__ __forceinline__ void gemm8(const float* __restrict__ w,
                                      const float* __restrict__ a,
                                      int og, int pg, u64 acc[4][4])
{
#pragma unroll 4
    for (int k = 0; k < KS; k++) {
        const float* wr = w + k*68 + og*8;
        ulonglong2 w01 = *(const ulonglong2*)wr;
        ulonglong2 w23 = *(const ulonglong2*)(wr+4);
        u64 wp[4] = {w01.x,w01.y,w23.x,w23.y};
        float4 av = *(const float4*)(a + k*68 + pg*4);
        u64 as[4] = {pk2(av.x,av.x), pk2(av.y,av.y), pk2(av.z,av.z), pk2(av.w,av.w)};
#pragma unroll
        for (int op = 0; op < 4; op++)
#pragma unroll
            for (int p = 0; p < 4; p++) fma2(acc[op][p], wp[op], as[p]);
    }
}

// =====================================================================
// Fused kernel: 64-pos tile, 128 threads, 3 CTAs/SM, pipelined weights
// =====================================================================
__global__ void __launch_bounds__(128,3) fused_kernel(
    const float* __restrict__ xyz,
    const float* __restrict__ w1sc, const float* __restrict__ b1sc,
    const float* __restrict__ w1a,  const float* __restrict__ b1a,
    const float* __restrict__ w1b,  const float* __restrict__ b1b,
    const float* __restrict__ w1c,  const float* __restrict__ b1c,
    const float* __restrict__ w2sc, const float* __restrict__ b2sc,
    const float* __restrict__ w2a,  const float* __restrict__ b2a,
    const float* __restrict__ w2b,  const float* __restrict__ b2b,
    const float* __restrict__ w2c,  const float* __restrict__ b2c,
    float* __restrict__ outp)
{
    extern __shared__ float sm[];
    const int tid = threadIdx.x;
    const int pg = tid & 15, og = tid >> 4;
    const int base = blockIdx.x << 6;
    const int b  = base >> 17;
    const int n0 = (base & (NPTS*KNB - 1)) >> 4;
    const int nl = pg >> 2;

    float4 R[4];

    // ---- prologue: LDG chunk0 (w1b lo); features/smallW/biases; STS c0 ----
    ldgA<64>(R, w1b, 0, tid);
    for (int l = tid; l < 640; l += 128) {
        int o = l/10, k = l - o*10;
        sm[SC + 680  + k*68 + o] = w1sc[l];
        sm[SC + 1360 + k*68 + o] = w1a[l];
    }
    if (tid < 64) {
        sm[SBIAS+tid] = b1sc[tid]; sm[SBIAS+64+tid] = b1a[tid];
        sm[SBIAS+128+tid] = b1b[tid]; sm[SBIAS+192+tid] = b1c[tid];
    }
    if (tid < 64) {
        int nn = n0 + (tid >> 4);
        const float* xb = xyz + b*3*NPTS;
        int j = g_idx[(b*NPTS + nn)*KNB + (tid & 15)];
        float cx = xb[nn], cy = xb[NPTS+nn], cz = xb[2*NPTS+nn];
        float nx = xb[j],  ny = xb[NPTS+j],  nz = xb[2*NPTS+j];
        float rx = nx-cx, ry = ny-cy, rz = nz-cz;
        float dd = sqrtf(fmaf(rx,rx, fmaf(ry,ry, rz*rz)) + 1e-12f);
        sm[SC+0*68+tid]=cx; sm[SC+1*68+tid]=cy; sm[SC+2*68+tid]=cz;
        sm[SC+3*68+tid]=nx; sm[SC+4*68+tid]=ny; sm[SC+5*68+tid]=nz;
        sm[SC+6*68+tid]=rx; sm[SC+7*68+tid]=ry; sm[SC+8*68+tid]=rz;
        sm[SC+9*68+tid]=dd;
    }
    stsA(sm + SW0, R, tid);
    __syncthreads();

    // ---- P1: stage1 sc + a (K=10); h->SA, sc->SB ----
    {
        u64 accS[4][4], accA[4][4];
#pragma unroll
        for (int op=0;op<4;op++)
#pragma unroll
            for (int p=0;p<4;p++) { accS[op][p]=0ull; accA[op][p]=0ull; }
#pragma unroll
        for (int k = 0; k < 10; k++) {
            const float* wsr = sm + SC + 680  + k*68 + og*8;
            const float* war = sm + SC + 1360 + k*68 + og*8;
            ulonglong2 ws01 = *(const ulonglong2*)wsr;
            ulonglong2 ws23 = *(const ulonglong2*)(wsr+4);
            ulonglong2 wa01 = *(const ulonglong2*)war;
            ulonglong2 wa23 = *(const ulonglong2*)(war+4);
            u64 wsp[4] = {ws01.x,ws01.y,ws23.x,ws23.y};
            u64 wap[4] = {wa01.x,wa01.y,wa23.x,wa23.y};
            float4 av = *(const float4*)(sm + SC + k*68 + pg*4);
            u64 as[4] = {pk2(av.x,av.x), pk2(av.y,av.y), pk2(av.z,av.z), pk2(av.w,av.w)};
#pragma unroll
            for (int op=0;op<4;op++)
#pragma unroll
                for (int p=0;p<4;p++) { fma2(accS[op][p], wsp[op], as[p]); fma2(accA[op][p], wap[op], as[p]); }
        }
#pragma unroll
        for (int op=0;op<4;op++) {
            int o0 = og*8 + 2*op;
            float ba0 = sm[SBIAS+64+o0], ba1 = sm[SBIAS+64+o0+1];
#pragma unroll
            for (int p=0;p<4;p++) {
                float2 va = up2(accA[op][p]);
                sm[SA + (o0  )*68 + pg*4 + p] = leaky(va.x + ba0);
                sm[SA + (o0+1)*68 + pg*4 + p] = leaky(va.y + ba1);
                float2 vs = up2(accS[op][p]);
                sm[SB + (o0  )*68 + pg*4 + p] = vs.x;
                sm[SB + (o0+1)*68 + pg*4 + p] = vs.y;
            }
        }
    }
    __syncthreads();

    u64 acc4[4][4];
#define ZERO4 {_Pragma("unroll") for (int op=0;op<4;op++) _Pragma("unroll") for (int p=0;p<4;p++) acc4[op][p]=0ull;}

    // ---- p0: w1b lo on SA ----
    ldgA<64>(R, w1b, 32, tid);
    ZERO4
    gemm8<32>(sm + SW0, sm + SA, og, pg, acc4);
    stsA(sm + SW1, R, tid);
    __syncthreads();

    // ---- p1: w1b hi on SA ; epi h2 -> SC ----
    ldgA<64>(R, w1c, 0, tid);
    gemm8<32>(sm + SW1, sm + SA + 32*68, og, pg, acc4);
#pragma unroll
    for (int op=0;op<4;op++) {
        int o0 = og*8 + 2*op;
        float b0 = sm[SBIAS+128+o0], b1 = sm[SBIAS+128+o0+1];
#pragma unroll
        for (int p=0;p<4;p++) {
            float2 v = up2(acc4[op][p]);
            sm[SC + (o0  )*68 + pg*4 + p] = leaky(v.x + b0);
            sm[SC + (o0+1)*68 + pg*4 + p] = leaky(v.y + b1);
        }
    }
    stsA(sm + SW0, R, tid);
    __syncthreads();

    // ---- p2: w1c lo on SC ----
    ldgA<64>(R, w1c, 32, tid);
    ZERO4
    gemm8<32>(sm + SW0, sm + SC, og, pg, acc4);
    stsA(sm + SW1, R, tid);
    __syncthreads();

    // ---- p3: w1c hi ; epi out1 -> SB (+sc), x1 -> SX1 ----
    ldgA<128>(R, w2a, 0, tid);
    gemm8<32>(sm + SW1, sm + SC + 32*68, og, pg, acc4);
#pragma unroll
    for (int op=0;op<4;op++) {
        int o0 = og*8 + 2*op;
        float bt0 = sm[SBIAS+192+o0] + sm[SBIAS+o0];
        float bt1 = sm[SBIAS+192+o0+1] + sm[SBIAS+o0+1];
        float v0m = -3.4e38f, v1m = -3.4e38f;
#pragma unroll
        for (int p=0;p<4;p++) {
            float2 v = up2(acc4[op][p]);
            float o0v = v.x + sm[SB + (o0  )*68 + pg*4 + p] + bt0;
            float o1v = v.y + sm[SB + (o0+1)*68 + pg*4 + p] + bt1;
            sm[SB + (o0  )*68 + pg*4 + p] = o0v;
            sm[SB + (o0+1)*68 + pg*4 + p] = o1v;
            v0m = fmaxf(v0m, o0v); v1m = fmaxf(v1m, o1v);
        }
        v0m = fmaxf(v0m, __shfl_xor_sync(0xffffffffu, v0m, 1));
        v0m = fmaxf(v0m, __shfl_xor_sync(0xffffffffu, v0m, 2));
        v1m = fmaxf(v1m, __shfl_xor_sync(0xffffffffu, v1m, 1));
        v1m = fmaxf(v1m, __shfl_xor_sync(0xffffffffu, v1m, 2));
        if ((pg & 3) == 0) {
            sm[SX1 + (o0  )*4 + nl] = v0m;
            sm[SX1 + (o0+1)*4 + nl] = v1m;
        }
    }
    stsA(sm + SW0, R, tid);
    __syncthreads();

    // ---- p4: w2a main lo on SB ----
    ldgA<128>(R, w2a, 32, tid);
    ZERO4
    gemm8<32>(sm + SW0, sm + SB, og, pg, acc4);
    stsA(sm + SW1, R, tid);
    __syncthreads();

    // ---- p5: w2a main hi ----
    ldgA<128>(R, w2a, 64, tid);
    gemm8<32>(sm + SW1, sm + SB + 32*68, og, pg, acc4);
    stsA(sm + SW0, R, tid);
    __syncthreads();

    // ---- p6: w2a corr c0..31 ----
    u64 crA[4] = {0,0,0,0};
    ldgA<128>(R, w2a, 96, tid);
#pragma unroll 4
    for (int c = 0; c < 32; c++) {
        const float* wr = sm + SW0 + c*68 + og*8;
        ulonglong2 w01 = *(const ulonglong2*)wr;
        ulonglong2 w23 = *(const ulonglong2*)(wr+4);
        float xv = sm[SX1 + c*4 + nl];
        u64 xs = pk2(xv, xv);
        fma2(crA[0], w01.x, xs); fma2(crA[1], w01.y, xs);
        fma2(crA[2], w23.x, xs); fma2(crA[3], w23.y, xs);
    }
    stsA(sm + SW1, R, tid);
    __syncthreads();

    // ---- p7: w2a corr c32..63 ; epi h -> SA ----
    ldgB<64>(R, w2b, 0, tid);
#pragma unroll 4
    for (int c = 0; c < 32; c++) {
        const float* wr = sm + SW1 + c*68 + og*8;
        ulonglong2 w01 = *(const ulonglong2*)wr;
        ulonglong2 w23 = *(const ulonglong2*)(wr+4);
        float xv = sm[SX1 + (32+c)*4 + nl];
        u64 xs = pk2(xv, xv);
        fma2(crA[0], w01.x, xs); fma2(crA[1], w01.y, xs);
        fma2(crA[2], w23.x, xs); fma2(crA[3], w23.y, xs);
    }
#pragma unroll
    for (int op=0;op<4;op++) {
        int o0 = og*8 + 2*op;
        float2 c2 = up2(crA[op]);
        float b0 = __ldg(b2a + o0) + c2.x;
        float b1 = __ldg(b2a + o0 + 1) + c2.y;
#pragma unroll
        for (int p=0;p<4;p++) {
            float2 v = up2(acc4[op][p]);
            sm[SA + (o0  )*68 + pg*4 + p] = leaky(v.x + b0);
            sm[SA + (o0+1)*68 + pg*4 + p] = leaky(v.y + b1);
        }
    }
    stsB(sm + SW0, R, tid);
    __syncthreads();

    // ---- p8..p11: stage2 b (w2b, 4x16k) on SA(h) ----
    u64 acc[8][4];
#pragma unroll
    for (int op=0;op<8;op++)
#pragma unroll
        for (int p=0;p<4;p++) acc[op][p]=0ull;

    ldgB<64>(R, w2b, 16, tid);
    gemm16<16>(sm + SW0, sm + SA, og, pg, acc);
    stsB(sm + SW1, R, tid);
    __syncthreads();

    ldgB<64>(R, w2b, 32, tid);
    gemm16<16>(sm + SW1, sm + SA + 16*68, og, pg, acc);
    stsB(sm + SW0, R, tid);
    __syncthreads();

    ldgB<64>(R, w2b, 48, tid);
    gemm16<16>(sm + SW0, sm + SA + 32*68, og, pg, acc);
    stsB(sm + SW1, R, tid);
    __syncthreads();

    ldgB<128>(R, w2c, 0, tid);
    gemm16<16>(sm + SW1, sm + SA + 48*68, og, pg, acc);
    __syncthreads();   // all reads of SA done before h2 overwrite
#pragma unroll
    for (int op=0;op<8;op++) {
        int o0 = og*16 + 2*op;
        float b0 = __ldg(b2b + o0), b1 = __ldg(b2b + o0+1);
        float* d0 = sm + ((o0 < 64) ? (SA + o0*68) : (SC + (o0-64)*68));
        float* d1 = sm + ((o0+1 < 64) ? (SA + (o0+1)*68) : (SC + (o0+1-64)*68));
#pragma unroll
        for (int p=0;p<4;p++) {
            float2 v = up2(acc[op][p]);
            d0[pg*4 + p] = leaky(v.x + b0);
            d1[pg*4 + p] = leaky(v.y + b1);
        }
    }
    stsB(sm + SW0, R, tid);
    __syncthreads();

    // ---- p12..p19: stage2 c (w2c, 8x16k) ; p20..p23 sc main ----
#pragma unroll
    for (int op=0;op<8;op++)
#pragma unroll
        for (int p=0;p<4;p++) acc[op][p]=0ull;

    ldgB<128>(R, w2c, 16, tid);
    gemm16<16>(sm + SW0, sm + SA, og, pg, acc);
    stsB(sm + SW1, R, tid); __syncthreads();

    ldgB<128>(R, w2c, 32, tid);
    gemm16<16>(sm + SW1, sm + SA + 16*68, og, pg, acc);
    stsB(sm + SW0, R, tid); __syncthreads();

    ldgB<128>(R, w2c, 48, tid);
    gemm16<16>(sm + SW0, sm + SA + 32*68, og, pg, acc);
    stsB(sm + SW1, R, tid); __syncthreads();

    ldgB<128>(R, w2c, 64, tid);
    gemm16<16>(sm + SW1, sm + SA + 48*68, og, pg, acc);
    stsB(sm + SW0, R, tid); __syncthreads();

    ldgB<128>(R, w2c, 80, tid);
    gemm16<16>(sm + SW0, sm + SC, og, pg, acc);
    stsB(sm + SW1, R, tid); __syncthreads();

    ldgB<128>(R, w2c, 96, tid);
    gemm16<16>(sm + SW1, sm + SC + 16*68, og, pg, acc);
    stsB(sm + SW0, R, tid); __syncthreads();

    ldgB<128>(R, w2c, 112, tid);
    gemm16<16>(sm + SW0, sm + SC + 32*68, og, pg, acc);
    stsB(sm + SW1, R, tid); __syncthreads();

    ldgB<128>(R, w2sc, 0, tid);
    gemm16<16>(sm + SW1, sm + SC + 48*68, og, pg, acc);
    stsB(sm + SW0, R, tid); __syncthreads();

    ldgB<128>(R, w2sc, 16, tid);
    gemm16<16>(sm + SW0, sm + SB, og, pg, acc);
    stsB(sm + SW1, R, tid); __syncthreads();

    ldgB<128>(R, w2sc, 32, tid);
    gemm16<16>(sm + SW1, sm + SB + 16*68, og, pg, acc);
    stsB(sm + SW0, R, tid); __syncthreads();

    ldgB<128>(R, w2sc, 48, tid);
    gemm16<16>(sm + SW0, sm + SB + 32*68, og, pg, acc);
    stsB(sm + SW1, R, tid); __syncthreads();

    ldgB<128>(R, w2sc, 64, tid);
    gemm16<16>(sm + SW1, sm + SB + 48*68, og, pg, acc);
    stsB(sm + SW0, R, tid); __syncthreads();

    // ---- p24..p27: sc x1-corr (4 x 16 cols) ----
    u64 cr2[8] = {0,0,0,0,0,0,0,0};
#define CORR16(BUF, C0) \
    _Pragma("unroll 4") \
    for (int cc = 0; cc < 16; cc++) { \
        const float* wr = sm + (BUF) + cc*132 + og*16; \
        ulonglong2 w01 = *(const ulonglong2*)wr; \
        ulonglong2 w23 = *(const ulonglong2*)(wr+4); \
        ulonglong2 w45 = *(const ulonglong2*)(wr+8); \
        ulonglong2 w67 = *(const ulonglong2*)(wr+12); \
        float xv = sm[SX1 + ((C0)+cc)*4 + nl]; \
        u64 xs = pk2(xv, xv); \
        fma2(cr2[0], w01.x, xs); fma2(cr2[1], w01.y, xs); \
        fma2(cr2[2], w23.x, xs); fma2(cr2[3], w23.y, xs); \
        fma2(cr2[4], w45.x, xs); fma2(cr2[5], w45.y, xs); \
        fma2(cr2[6], w67.x, xs); fma2(cr2[7], w67.y, xs); \
    }

    ldgB<128>(R, w2sc, 80, tid);
    CORR16(SW0, 0)
    stsB(sm + SW1, R, tid); __syncthreads();

    ldgB<128>(R, w2sc, 96, tid);
    CORR16(SW1, 16)
    stsB(sm + SW0, R, tid); __syncthreads();

    ldgB<128>(R, w2sc, 112, tid);
    CORR16(SW0, 32)
    stsB(sm + SW1, R, tid); __syncthreads();

    CORR16(SW1, 48)

    // ---- epilogue ----
#pragma unroll
    for (int op=0;op<8;op++) {
        int o0 = og*16 + 2*op;
        float2 c2 = up2(cr2[op]);
        float bt0 = __ldg(b2sc + o0)     + __ldg(b2c + o0)     + c2.x;
        float bt1 = __ldg(b2sc + o0 + 1) + __ldg(b2c + o0 + 1) + c2.y;
        float m0 = -3.4e38f, m1 = -3.4e38f;
#pragma unroll
        for (int p=0;p<4;p++) {
            float2 v = up2(acc[op][p]);
            m0 = fmaxf(m0, v.x); m1 = fmaxf(m1, v.y);
        }
        m0 += bt0; m1 += bt1;
        m0 = fmaxf(m0, __shfl_xor_sync(0xffffffffu, m0, 1));
        m0 = fmaxf(m0, __shfl_xor_sync(0xffffffffu, m0, 2));
        m1 = fmaxf(m1, __shfl_xor_sync(0xffffffffu, m1, 1));
        m1 = fmaxf(m1, __shfl_xor_sync(0xffffffffu, m1, 2));
        if ((pg & 3) == 0) {
            outp[((long long)b*128 + o0    )*NPTS + n0 + nl] = m0;
            outp[((long long)b*128 + o0 + 1)*NPTS + n0 + nl] = m1;
        }
    }
}

// =====================================================================
extern "C" void kernel_launch(void* const* d_in, const int* in_sizes, int n_in,
                              void* d_out, int out_size)
{
    const float* xyz     = (const float*)d_in[0];
    const float* p1_sc_w = (const float*)d_in[1];
    const float* p1_sc_b = (const float*)d_in[2];
    const float* p1_a_w  = (const float*)d_in[3];
    const float* p1_a_b  = (const float*)d_in[4];
    const float* p1_b_w  = (const float*)d_in[5];
    const float* p1_b_b  = (const float*)d_in[6];
    const float* p1_c_w  = (const float*)d_in[7];
    const float* p1_c_b  = (const float*)d_in[8];
    const float* p2_sc_w = (const float*)d_in[9];
    const float* p2_sc_b = (const float*)d_in[10];
    const float* p2_a_w  = (const float*)d_in[11];
    const float* p2_a_b  = (const float*)d_in[12];
    const float* p2_b_w  = (const float*)d_in[13];
    const float* p2_b_b  = (const float*)d_in[14];
    const float* p2_c_w  = (const float*)d_in[15];
    const float* p2_c_b  = (const float*)d_in[16];
    float* outp = (float*)d_out;

    cudaFuncSetAttribute(fused_kernel, cudaFuncAttributeMaxDynamicSharedMemorySize,
                         SMEM_FLOATS*4);

    knn_part<<<BATCH*64*NPART, 128, 32768>>>(xyz);
    knn_merge<<<NQ/256, 256>>>();
    fused_kernel<<<NPOS/64, 128, SMEM_FLOATS*4>>>(
        xyz,
        p1_sc_w, p1_sc_b, p1_a_w, p1_a_b, p1_b_w, p1_b_b, p1_c_w, p1_c_b,
        p2_sc_w, p2_sc_b, p2_a_w, p2_a_b, p2_b_w, p2_b_b, p2_c_w, p2_c_b,
        outp);
}